// round 2
// baseline (speedup 1.0000x reference)
#include <cuda_runtime.h>

// Problem dims
#define NB   4
#define NS   2048
#define ND   1024
#define NH   16
#define NDH  64
#define NBH  (NB * NH)     // 64
#define NM   (NB * NS)     // 8192 tokens
#define N_QKV (3 * ND)     // 3072
#define INV_SCALE 0.125f   // 1/sqrt(64)

// Scratch (static __device__ arrays: allocation-free per harness rules)
__device__ float g_Q[(size_t)NBH * NS * NDH];     // [bh][s][dh], pre-scaled by 1/8
__device__ float g_K[(size_t)NBH * NS * NDH];
__device__ float g_V[(size_t)NBH * NS * NDH];
__device__ float g_ctx[(size_t)NM * ND];          // [b][s][d] ready for out-proj

// ---------------------------------------------------------------------------
// GEMM 1: QKV projection.  C[8192,3072] = A[8192,1024] @ W[1024,3072] + b,
// scattered directly into Q/K/V in [bh][s][dh] layout (interleave n = h*192 + dh*3 + t).
// 128x128 tile, BK=8, 256 threads, 8x8 micro-tile per thread.
// ---------------------------------------------------------------------------
__global__ __launch_bounds__(256) void qkv_gemm_kernel(
    const float* __restrict__ A,
    const float* __restrict__ W,
    const float* __restrict__ bias)
{
    const int K = ND;
    const int N = N_QKV;
    __shared__ float As[8][128];   // transposed A tile
    __shared__ float Bs[8][128];

    int tid = threadIdx.x;
    int m0 = blockIdx.y * 128;
    int n0 = blockIdx.x * 128;
    int tx = tid & 15, ty = tid >> 4;

    float acc[8][8];
    #pragma unroll
    for (int i = 0; i < 8; i++)
        #pragma unroll
        for (int j = 0; j < 8; j++) acc[i][j] = 0.f;

    int la_r = tid >> 1;             // 0..127
    int la_c = (tid & 1) * 4;        // 0 or 4
    int lb_r = tid >> 5;             // 0..7
    int lb_c = (tid & 31) * 4;       // 0..124

    const float* Aptr = A + (size_t)(m0 + la_r) * K + la_c;
    const float* Wptr = W + (size_t)lb_r * N + n0 + lb_c;

    for (int k0 = 0; k0 < K; k0 += 8) {
        float4 a = *(const float4*)(Aptr + k0);
        float4 b = *(const float4*)(Wptr + (size_t)k0 * N);
        As[la_c + 0][la_r] = a.x;
        As[la_c + 1][la_r] = a.y;
        As[la_c + 2][la_r] = a.z;
        As[la_c + 3][la_r] = a.w;
        *(float4*)&Bs[lb_r][lb_c] = b;
        __syncthreads();
        #pragma unroll
        for (int k = 0; k < 8; k++) {
            float ar[8], br[8];
            *(float4*)&ar[0] = *(const float4*)&As[k][ty * 8];
            *(float4*)&ar[4] = *(const float4*)&As[k][ty * 8 + 4];
            *(float4*)&br[0] = *(const float4*)&Bs[k][tx * 8];
            *(float4*)&br[4] = *(const float4*)&Bs[k][tx * 8 + 4];
            #pragma unroll
            for (int i = 0; i < 8; i++)
                #pragma unroll
                for (int j = 0; j < 8; j++)
                    acc[i][j] += ar[i] * br[j];
        }
        __syncthreads();
    }

    // Epilogue: scatter into Q/K/V.  n -> (h, dh, t) with n = h*192 + dh*3 + t.
    int hh[8], dd[8], tt[8];
    float bb[8];
    #pragma unroll
    for (int j = 0; j < 8; j++) {
        int n = n0 + tx * 8 + j;
        hh[j] = n / 192;
        int rem = n - hh[j] * 192;
        dd[j] = rem / 3;
        tt[j] = rem - dd[j] * 3;
        bb[j] = bias[n];
    }
    #pragma unroll
    for (int i = 0; i < 8; i++) {
        int m = m0 + ty * 8 + i;
        int bi = m >> 11;           // / 2048
        int si = m & (NS - 1);
        #pragma unroll
        for (int j = 0; j < 8; j++) {
            float v = acc[i][j] + bb[j];
            size_t idx = ((size_t)(bi * NH + hh[j]) * NS + si) * NDH + dd[j];
            if (tt[j] == 0)      g_Q[idx] = v * INV_SCALE;
            else if (tt[j] == 1) g_K[idx] = v;
            else                 g_V[idx] = v;
        }
    }
}

// ---------------------------------------------------------------------------
// Causal flash attention.  One block = (bh, 64-row q tile).  64x64 KV tiles,
// online softmax in fp32.  P tile aliases the K tile so the 3 tiles fit the
// 48KB static smem limit exactly.  Thread (r = tid/4, c = tid%4) owns row r,
// score slice k in [c*16, c*16+16), output dims [c*16, c*16+16).
// ---------------------------------------------------------------------------
__global__ __launch_bounds__(256) void attn_kernel()
{
    __shared__ float Qs[64 * 64];
    __shared__ float KPs[64 * 64];   // K tile, reused as P tile after scores
    __shared__ float Vs[64 * 64];

    int tid = threadIdx.x;
    int bh  = blockIdx.y;
    int qt  = blockIdx.x;
    int q0  = qt * 64;
    int r   = tid >> 2;
    int c   = tid & 3;
    int q_global = q0 + r;

    int lr = tid >> 4;             // 0..15
    int lc = (tid & 15) * 4;       // 0..60

    const float* Qg = g_Q + ((size_t)bh * NS + q0) * NDH;
    #pragma unroll
    for (int it = 0; it < 4; it++)
        *(float4*)&Qs[(lr + it * 16) * 64 + lc] =
            *(const float4*)(Qg + (size_t)(lr + it * 16) * 64 + lc);

    float o[16];
    #pragma unroll
    for (int j = 0; j < 16; j++) o[j] = 0.f;
    float m_run = -1e30f, l_run = 0.f;
    __syncthreads();

    for (int kt = 0; kt <= qt; kt++) {
        int k0 = kt * 64;
        const float* Kg = g_K + ((size_t)bh * NS + k0) * NDH;
        const float* Vg = g_V + ((size_t)bh * NS + k0) * NDH;
        #pragma unroll
        for (int it = 0; it < 4; it++) {
            *(float4*)&KPs[(lr + it * 16) * 64 + lc] =
                *(const float4*)(Kg + (size_t)(lr + it * 16) * 64 + lc);
            *(float4*)&Vs[(lr + it * 16) * 64 + lc] =
                *(const float4*)(Vg + (size_t)(lr + it * 16) * 64 + lc);
        }
        __syncthreads();

        // scores: s[kk] = q_row(r) . k_row(c*16+kk)
        float s[16];
        #pragma unroll
        for (int kk = 0; kk < 16; kk++) s[kk] = 0.f;
        #pragma unroll
        for (int d0 = 0; d0 < 64; d0 += 4) {
            float4 q4 = *(const float4*)&Qs[r * 64 + d0];
            #pragma unroll
            for (int kk = 0; kk < 16; kk++) {
                float4 k4 = *(const float4*)&KPs[(c * 16 + kk) * 64 + d0];
                s[kk] += q4.x * k4.x;
                s[kk] += q4.y * k4.y;
                s[kk] += q4.z * k4.z;
                s[kk] += q4.w * k4.w;
            }
        }

        // causal mask: only the diagonal tile is partial
        if (kt == qt) {
            #pragma unroll
            for (int kk = 0; kk < 16; kk++)
                if (k0 + c * 16 + kk > q_global) s[kk] = -1e30f;
        }

        // online softmax (row spread across 4 adjacent lanes)
        float mloc = s[0];
        #pragma unroll
        for (int kk = 1; kk < 16; kk++) mloc = fmaxf(mloc, s[kk]);
        mloc = fmaxf(mloc, __shfl_xor_sync(0xffffffffu, mloc, 1));
        mloc = fmaxf(mloc, __shfl_xor_sync(0xffffffffu, mloc, 2));
        float m_new = fmaxf(m_run, mloc);
        float alpha = __expf(m_run - m_new);
        float lloc = 0.f;
        #pragma unroll
        for (int kk = 0; kk < 16; kk++) {
            float p = __expf(s[kk] - m_new);
            s[kk] = p;
            lloc += p;
        }
        lloc += __shfl_xor_sync(0xffffffffu, lloc, 1);
        lloc += __shfl_xor_sync(0xffffffffu, lloc, 2);
        l_run = l_run * alpha + lloc;
        m_run = m_new;
        #pragma unroll
        for (int j = 0; j < 16; j++) o[j] *= alpha;

        __syncthreads();   // all K-tile reads done before aliasing as P
        #pragma unroll
        for (int qi = 0; qi < 4; qi++)
            *(float4*)&KPs[r * 64 + c * 16 + qi * 4] =
                make_float4(s[qi * 4 + 0], s[qi * 4 + 1],
                            s[qi * 4 + 2], s[qi * 4 + 3]);
        __syncthreads();

        // O += P @ V
        #pragma unroll
        for (int kq = 0; kq < 64; kq += 4) {
            float4 p4 = *(const float4*)&KPs[r * 64 + kq];
            float pvals[4] = {p4.x, p4.y, p4.z, p4.w};
            #pragma unroll
            for (int u = 0; u < 4; u++) {
                float pv = pvals[u];
                const float* vrow = &Vs[(kq + u) * 64 + c * 16];
                float4 va = *(const float4*)(vrow + 0);
                float4 vb = *(const float4*)(vrow + 4);
                float4 vc = *(const float4*)(vrow + 8);
                float4 vd = *(const float4*)(vrow + 12);
                o[0]  += pv * va.x;  o[1]  += pv * va.y;
                o[2]  += pv * va.z;  o[3]  += pv * va.w;
                o[4]  += pv * vb.x;  o[5]  += pv * vb.y;
                o[6]  += pv * vb.z;  o[7]  += pv * vb.w;
                o[8]  += pv * vc.x;  o[9]  += pv * vc.y;
                o[10] += pv * vc.z;  o[11] += pv * vc.w;
                o[12] += pv * vd.x;  o[13] += pv * vd.y;
                o[14] += pv * vd.z;  o[15] += pv * vd.w;
            }
        }
        __syncthreads();   // P/V reads done before next tile overwrites
    }

    float inv_l = 1.f / l_run;
    int bi = bh >> 4;
    int h  = bh & 15;
    float* dst = g_ctx + ((size_t)bi * NS + q_global) * ND + h * NDH + c * 16;
    #pragma unroll
    for (int qi = 0; qi < 4; qi++)
        *(float4*)(dst + qi * 4) =
            make_float4(o[qi * 4 + 0] * inv_l, o[qi * 4 + 1] * inv_l,
                        o[qi * 4 + 2] * inv_l, o[qi * 4 + 3] * inv_l);
}

// ---------------------------------------------------------------------------
// GEMM 2: output projection.  out[8192,1024] = ctx[8192,1024] @ W_out + b_out.
// ---------------------------------------------------------------------------
__global__ __launch_bounds__(256) void out_gemm_kernel(
    const float* __restrict__ W,
    const float* __restrict__ bias,
    float* __restrict__ out)
{
    const int K = ND;
    const int N = ND;
    __shared__ float As[8][128];
    __shared__ float Bs[8][128];

    int tid = threadIdx.x;
    int m0 = blockIdx.y * 128;
    int n0 = blockIdx.x * 128;
    int tx = tid & 15, ty = tid >> 4;

    float acc[8][8];
    #pragma unroll
    for (int i = 0; i < 8; i++)
        #pragma unroll
        for (int j = 0; j < 8; j++) acc[i][j] = 0.f;

    int la_r = tid >> 1;
    int la_c = (tid & 1) * 4;
    int lb_r = tid >> 5;
    int lb_c = (tid & 31) * 4;

    const float* Aptr = g_ctx + (size_t)(m0 + la_r) * K + la_c;
    const float* Wptr = W + (size_t)lb_r * N + n0 + lb_c;

    for (int k0 = 0; k0 < K; k0 += 8) {
        float4 a = *(const float4*)(Aptr + k0);
        float4 b = *(const float4*)(Wptr + (size_t)k0 * N);
        As[la_c + 0][la_r] = a.x;
        As[la_c + 1][la_r] = a.y;
        As[la_c + 2][la_r] = a.z;
        As[la_c + 3][la_r] = a.w;
        *(float4*)&Bs[lb_r][lb_c] = b;
        __syncthreads();
        #pragma unroll
        for (int k = 0; k < 8; k++) {
            float ar[8], br[8];
            *(float4*)&ar[0] = *(const float4*)&As[k][ty * 8];
            *(float4*)&ar[4] = *(const float4*)&As[k][ty * 8 + 4];
            *(float4*)&br[0] = *(const float4*)&Bs[k][tx * 8];
            *(float4*)&br[4] = *(const float4*)&Bs[k][tx * 8 + 4];
            #pragma unroll
            for (int i = 0; i < 8; i++)
                #pragma unroll
                for (int j = 0; j < 8; j++)
                    acc[i][j] += ar[i] * br[j];
        }
        __syncthreads();
    }

    #pragma unroll
    for (int i = 0; i < 8; i++) {
        int m = m0 + ty * 8 + i;
        #pragma unroll
        for (int j = 0; j < 8; j += 4) {
            int n = n0 + tx * 8 + j;
            float4 v = make_float4(acc[i][j + 0] + bias[n + 0],
                                   acc[i][j + 1] + bias[n + 1],
                                   acc[i][j + 2] + bias[n + 2],
                                   acc[i][j + 3] + bias[n + 3]);
            *(float4*)(out + (size_t)m * N + n) = v;
        }
    }
}

// ---------------------------------------------------------------------------
// Launch: three stream-ordered kernels (graph-capturable, allocation-free).
// Inputs (metadata order): query, mask(unused — causal is static), W_qkv,
// b_qkv, W_out, b_out.
// ---------------------------------------------------------------------------
extern "C" void kernel_launch(void* const* d_in, const int* in_sizes, int n_in,
                              void* d_out, int out_size)
{
    const float* query = (const float*)d_in[0];
    const float* W_qkv = (const float*)d_in[2];
    const float* b_qkv = (const float*)d_in[3];
    const float* W_out = (const float*)d_in[4];
    const float* b_out = (const float*)d_in[5];
    float* out = (float*)d_out;

    qkv_gemm_kernel<<<dim3(N_QKV / 128, NM / 128), 256>>>(query, W_qkv, b_qkv);
    attn_kernel<<<dim3(NS / 64, NBH), 256>>>();
    out_gemm_kernel<<<dim3(ND / 128, NM / 128), 256>>>(W_out, b_out, out);
}

// round 3
// speedup vs baseline: 8.3697x; 8.3697x over previous
#include <cuda_runtime.h>

// Problem dims
#define NB   4
#define NS   2048
#define ND   1024
#define NH   16
#define NDH  64
#define NBH  (NB * NH)     // 64
#define NM   (NB * NS)     // 8192 tokens
#define N_QKV (3 * ND)     // 3072
#define INV_SCALE 0.125f   // 1/sqrt(64)

// Scratch (static __device__ arrays: allocation-free per harness rules)
// Q/K/V are stored ALREADY ROUNDED to tf32 (bit-pattern in fp32) by the QKV epilogue.
__device__ float g_Q[(size_t)NBH * NS * NDH];     // [bh][s][dh], pre-scaled by 1/8
__device__ float g_K[(size_t)NBH * NS * NDH];
__device__ float g_V[(size_t)NBH * NS * NDH];
__device__ float g_ctx[(size_t)NM * ND];          // [b][s][d] ready for out-proj

// ---------------------------------------------------------------------------
// tf32 helpers
// ---------------------------------------------------------------------------
__device__ __forceinline__ unsigned f2tf(float x) {
    unsigned u;
    asm("cvt.rna.tf32.f32 %0, %1;" : "=r"(u) : "f"(x));
    return u;
}

// D = A(16x8) * B(8x8) + D, tf32 inputs, fp32 accumulate.
// A frag: a0=(g,tg) a1=(g+8,tg) a2=(g,tg+4) a3=(g+8,tg+4)   [g=lane>>2, tg=lane&3]
// B frag (col-major k x n): b0=(tg, g) b1=(tg+4, g)
// C frag: c0=(g, 2tg) c1=(g, 2tg+1) c2=(g+8, 2tg) c3=(g+8, 2tg+1)
__device__ __forceinline__ void mma8(float* c,
                                     unsigned a0, unsigned a1, unsigned a2, unsigned a3,
                                     unsigned b0, unsigned b1) {
    asm volatile(
        "mma.sync.aligned.m16n8k8.row.col.f32.tf32.tf32.f32 "
        "{%0,%1,%2,%3},{%4,%5,%6,%7},{%8,%9},{%0,%1,%2,%3};"
        : "+f"(c[0]), "+f"(c[1]), "+f"(c[2]), "+f"(c[3])
        : "r"(a0), "r"(a1), "r"(a2), "r"(a3), "r"(b0), "r"(b1));
}

// ---------------------------------------------------------------------------
// GEMM 1: QKV projection.  C[8192,3072] = A[8192,1024] @ W[1024,3072] + b,
// tf32 mma, 128x128 block tile, BK=32, 8 warps in 2x4 grid (warp tile 64x32),
// scatter epilogue into Q/K/V (n = h*192 + dh*3 + t), Q pre-scaled, all
// rounded to tf32 so the attention kernel can mma directly.
// ---------------------------------------------------------------------------
__global__ __launch_bounds__(256) void qkv_gemm_kernel(
    const float* __restrict__ A,
    const float* __restrict__ W,
    const float* __restrict__ bias)
{
    const int K = ND;
    const int N = N_QKV;
    __shared__ unsigned As[128][36];   // pad 36: frag loads bank = lane
    __shared__ unsigned Bs[32][132];   // pad 132: frag loads bank = lane

    int tid  = threadIdx.x;
    int m0   = blockIdx.y * 128;
    int n0   = blockIdx.x * 128;
    int warp = tid >> 5, lane = tid & 31;
    int wm   = warp >> 2, wn = warp & 3;      // 2 x 4 warp grid
    int g    = lane >> 2, tg = lane & 3;

    float acc[4][4][4];
    #pragma unroll
    for (int i = 0; i < 4; i++)
        #pragma unroll
        for (int j = 0; j < 4; j++)
            #pragma unroll
            for (int e = 0; e < 4; e++) acc[i][j][e] = 0.f;

    int a_r = tid >> 3;           // 0..31  (+i*32)
    int a_c = (tid & 7) * 4;      // 0..28
    int b_r = tid >> 5;           // 0..7   (+i*8)
    int b_c = (tid & 31) * 4;     // 0..124

    for (int k0 = 0; k0 < K; k0 += 32) {
        #pragma unroll
        for (int i = 0; i < 4; i++) {
            float4 a = *(const float4*)(A + (size_t)(m0 + a_r + i * 32) * K + k0 + a_c);
            As[a_r + i * 32][a_c + 0] = f2tf(a.x);
            As[a_r + i * 32][a_c + 1] = f2tf(a.y);
            As[a_r + i * 32][a_c + 2] = f2tf(a.z);
            As[a_r + i * 32][a_c + 3] = f2tf(a.w);
            float4 b = *(const float4*)(W + (size_t)(k0 + b_r + i * 8) * N + n0 + b_c);
            Bs[b_r + i * 8][b_c + 0] = f2tf(b.x);
            Bs[b_r + i * 8][b_c + 1] = f2tf(b.y);
            Bs[b_r + i * 8][b_c + 2] = f2tf(b.z);
            Bs[b_r + i * 8][b_c + 3] = f2tf(b.w);
        }
        __syncthreads();
        #pragma unroll
        for (int kk = 0; kk < 4; kk++) {
            int kb = kk * 8;
            unsigned af[4][4], bf[4][2];
            #pragma unroll
            for (int i = 0; i < 4; i++) {
                int row = wm * 64 + i * 16 + g;
                af[i][0] = As[row][kb + tg];
                af[i][1] = As[row + 8][kb + tg];
                af[i][2] = As[row][kb + tg + 4];
                af[i][3] = As[row + 8][kb + tg + 4];
            }
            #pragma unroll
            for (int j = 0; j < 4; j++) {
                int col = wn * 32 + j * 8 + g;
                bf[j][0] = Bs[kb + tg][col];
                bf[j][1] = Bs[kb + tg + 4][col];
            }
            #pragma unroll
            for (int i = 0; i < 4; i++)
                #pragma unroll
                for (int j = 0; j < 4; j++)
                    mma8(acc[i][j], af[i][0], af[i][1], af[i][2], af[i][3],
                         bf[j][0], bf[j][1]);
        }
        __syncthreads();
    }

    // Epilogue scatter.  n -> (h, dh, t) with n = h*192 + dh*3 + t.
    int hh[4][2], dd[4][2], tt[4][2];
    float bb[4][2];
    #pragma unroll
    for (int j = 0; j < 4; j++)
        #pragma unroll
        for (int e = 0; e < 2; e++) {
            int n = n0 + wn * 32 + j * 8 + 2 * tg + e;
            hh[j][e] = n / 192;
            int rem = n - hh[j][e] * 192;
            dd[j][e] = rem / 3;
            tt[j][e] = rem - dd[j][e] * 3;
            bb[j][e] = bias[n];
        }
    #pragma unroll
    for (int i = 0; i < 4; i++) {
        #pragma unroll
        for (int half = 0; half < 2; half++) {
            int m  = m0 + wm * 64 + i * 16 + g + half * 8;
            int bi = m >> 11;
            int si = m & (NS - 1);
            #pragma unroll
            for (int j = 0; j < 4; j++)
                #pragma unroll
                for (int e = 0; e < 2; e++) {
                    float v = acc[i][j][half * 2 + e] + bb[j][e];
                    size_t idx = ((size_t)(bi * NH + hh[j][e]) * NS + si) * NDH + dd[j][e];
                    if (tt[j][e] == 0)      g_Q[idx] = __uint_as_float(f2tf(v * INV_SCALE));
                    else if (tt[j][e] == 1) g_K[idx] = __uint_as_float(f2tf(v));
                    else                    g_V[idx] = __uint_as_float(f2tf(v));
                }
        }
    }
}

// ---------------------------------------------------------------------------
// Causal flash attention with tf32 mma.
// One block = (bh, 64-row q tile).  4 warps, warp w owns q rows 16w..16w+15.
// Tiles Qs/KPs/Vs are [64][68] fp32 (tf32-rounded) in dynamic smem; the P tile
// aliases the K tile after S-phase reads complete.
// ---------------------------------------------------------------------------
__global__ __launch_bounds__(128) void attn_kernel()
{
    extern __shared__ float smem[];
    float* Qs  = smem;                 // [64][68]
    float* KPs = smem + 64 * 68;       // [64][68]  K tile, reused as P
    float* Vs  = smem + 2 * 64 * 68;   // [64][68]

    int tid  = threadIdx.x;
    int bh   = blockIdx.y;
    int qt   = blockIdx.x;
    int q0   = qt * 64;
    int warp = tid >> 5, lane = tid & 31;
    int g    = lane >> 2, tg = lane & 3;

    int r0 = warp * 16 + g;            // row half 0
    int r1 = r0 + 8;                   // row half 1
    int qg0 = q0 + r0, qg1 = q0 + r1;

    // load Q tile (already tf32-rounded + 1/8-scaled in g_Q)
    const float* Qg = g_Q + ((size_t)bh * NS + q0) * NDH;
    #pragma unroll
    for (int it = 0; it < 8; it++) {
        int lin = tid + it * 128;              // 1024 float4 slots
        int row = lin >> 4, col = (lin & 15) * 4;
        *(float4*)&Qs[row * 68 + col] = *(const float4*)(Qg + (size_t)row * 64 + col);
    }

    float o[8][4];
    #pragma unroll
    for (int j = 0; j < 8; j++)
        #pragma unroll
        for (int e = 0; e < 4; e++) o[j][e] = 0.f;
    float m_run0 = -1e30f, m_run1 = -1e30f;
    float l_run0 = 0.f,    l_run1 = 0.f;
    __syncthreads();

    for (int kt = 0; kt <= qt; kt++) {
        int k0 = kt * 64;
        const float* Kg = g_K + ((size_t)bh * NS + k0) * NDH;
        const float* Vg = g_V + ((size_t)bh * NS + k0) * NDH;
        #pragma unroll
        for (int it = 0; it < 8; it++) {
            int lin = tid + it * 128;
            int row = lin >> 4, col = (lin & 15) * 4;
            *(float4*)&KPs[row * 68 + col] = *(const float4*)(Kg + (size_t)row * 64 + col);
            *(float4*)&Vs[row * 68 + col]  = *(const float4*)(Vg + (size_t)row * 64 + col);
        }
        __syncthreads();

        // ---- S = Q @ K^T  (m16 x n64 per warp) ----
        float sc[8][4];
        #pragma unroll
        for (int j = 0; j < 8; j++)
            #pragma unroll
            for (int e = 0; e < 4; e++) sc[j][e] = 0.f;
        #pragma unroll
        for (int kk = 0; kk < 8; kk++) {
            int kb = kk * 8;
            unsigned a0 = __float_as_uint(Qs[r0 * 68 + kb + tg]);
            unsigned a1 = __float_as_uint(Qs[r1 * 68 + kb + tg]);
            unsigned a2 = __float_as_uint(Qs[r0 * 68 + kb + tg + 4]);
            unsigned a3 = __float_as_uint(Qs[r1 * 68 + kb + tg + 4]);
            #pragma unroll
            for (int j = 0; j < 8; j++) {
                unsigned b0 = __float_as_uint(KPs[(j * 8 + g) * 68 + kb + tg]);
                unsigned b1 = __float_as_uint(KPs[(j * 8 + g) * 68 + kb + tg + 4]);
                mma8(sc[j], a0, a1, a2, a3, b0, b1);
            }
        }

        // causal mask (diagonal tile only is partial)
        if (kt == qt) {
            #pragma unroll
            for (int j = 0; j < 8; j++)
                #pragma unroll
                for (int e = 0; e < 2; e++) {
                    int kv = k0 + j * 8 + 2 * tg + e;
                    if (kv > qg0) sc[j][e]     = -1e30f;
                    if (kv > qg1) sc[j][2 + e] = -1e30f;
                }
        }

        // ---- online softmax (rows r0, r1; quad lanes share each row) ----
        float ml0 = -1e30f, ml1 = -1e30f;
        #pragma unroll
        for (int j = 0; j < 8; j++) {
            ml0 = fmaxf(ml0, fmaxf(sc[j][0], sc[j][1]));
            ml1 = fmaxf(ml1, fmaxf(sc[j][2], sc[j][3]));
        }
        ml0 = fmaxf(ml0, __shfl_xor_sync(0xffffffffu, ml0, 1));
        ml0 = fmaxf(ml0, __shfl_xor_sync(0xffffffffu, ml0, 2));
        ml1 = fmaxf(ml1, __shfl_xor_sync(0xffffffffu, ml1, 1));
        ml1 = fmaxf(ml1, __shfl_xor_sync(0xffffffffu, ml1, 2));
        float mn0 = fmaxf(m_run0, ml0);
        float mn1 = fmaxf(m_run1, ml1);
        float al0 = __expf(m_run0 - mn0);
        float al1 = __expf(m_run1 - mn1);
        float ls0 = 0.f, ls1 = 0.f;
        #pragma unroll
        for (int j = 0; j < 8; j++) {
            sc[j][0] = __expf(sc[j][0] - mn0);
            sc[j][1] = __expf(sc[j][1] - mn0);
            sc[j][2] = __expf(sc[j][2] - mn1);
            sc[j][3] = __expf(sc[j][3] - mn1);
            ls0 += sc[j][0] + sc[j][1];
            ls1 += sc[j][2] + sc[j][3];
        }
        ls0 += __shfl_xor_sync(0xffffffffu, ls0, 1);
        ls0 += __shfl_xor_sync(0xffffffffu, ls0, 2);
        ls1 += __shfl_xor_sync(0xffffffffu, ls1, 1);
        ls1 += __shfl_xor_sync(0xffffffffu, ls1, 2);
        l_run0 = l_run0 * al0 + ls0;
        l_run1 = l_run1 * al1 + ls1;
        m_run0 = mn0;
        m_run1 = mn1;
        #pragma unroll
        for (int j = 0; j < 8; j++) {
            o[j][0] *= al0;  o[j][1] *= al0;
            o[j][2] *= al1;  o[j][3] *= al1;
        }

        __syncthreads();   // all warps done reading K before aliasing as P

        // write P (tf32-rounded) to the aliased tile
        #pragma unroll
        for (int j = 0; j < 8; j++) {
            int cc = j * 8 + 2 * tg;
            *(float2*)&KPs[r0 * 68 + cc] =
                make_float2(__uint_as_float(f2tf(sc[j][0])),
                            __uint_as_float(f2tf(sc[j][1])));
            *(float2*)&KPs[r1 * 68 + cc] =
                make_float2(__uint_as_float(f2tf(sc[j][2])),
                            __uint_as_float(f2tf(sc[j][3])));
        }
        __syncwarp();      // each warp consumes only its own P rows

        // ---- O += P @ V  (m16 x n64 per warp) ----
        #pragma unroll
        for (int kk = 0; kk < 8; kk++) {
            int kb = kk * 8;
            unsigned a0 = __float_as_uint(KPs[r0 * 68 + kb + tg]);
            unsigned a1 = __float_as_uint(KPs[r1 * 68 + kb + tg]);
            unsigned a2 = __float_as_uint(KPs[r0 * 68 + kb + tg + 4]);
            unsigned a3 = __float_as_uint(KPs[r1 * 68 + kb + tg + 4]);
            #pragma unroll
            for (int j = 0; j < 8; j++) {
                unsigned b0 = __float_as_uint(Vs[(kb + tg) * 68 + j * 8 + g]);
                unsigned b1 = __float_as_uint(Vs[(kb + tg + 4) * 68 + j * 8 + g]);
                mma8(o[j], a0, a1, a2, a3, b0, b1);
            }
        }
        __syncthreads();   // P/V reads done before next tile overwrites
    }

    float inv0 = 1.f / l_run0;
    float inv1 = 1.f / l_run1;
    int bi = bh >> 4;
    int h  = bh & 15;
    float* d0 = g_ctx + ((size_t)(bi * NS) + qg0) * ND + h * NDH;
    float* d1 = g_ctx + ((size_t)(bi * NS) + qg1) * ND + h * NDH;
    #pragma unroll
    for (int j = 0; j < 8; j++) {
        int cc = j * 8 + 2 * tg;
        *(float2*)(d0 + cc) = make_float2(o[j][0] * inv0, o[j][1] * inv0);
        *(float2*)(d1 + cc) = make_float2(o[j][2] * inv1, o[j][3] * inv1);
    }
}

// ---------------------------------------------------------------------------
// GEMM 2: output projection.  out[8192,1024] = ctx[8192,1024] @ W_out + b_out.
// Same tf32 mma skeleton as GEMM 1, plain epilogue.
// ---------------------------------------------------------------------------
__global__ __launch_bounds__(256) void out_gemm_kernel(
    const float* __restrict__ W,
    const float* __restrict__ bias,
    float* __restrict__ out)
{
    const int K = ND;
    const int N = ND;
    __shared__ unsigned As[128][36];
    __shared__ unsigned Bs[32][132];

    int tid  = threadIdx.x;
    int m0   = blockIdx.y * 128;
    int n0   = blockIdx.x * 128;
    int warp = tid >> 5, lane = tid & 31;
    int wm   = warp >> 2, wn = warp & 3;
    int g    = lane >> 2, tg = lane & 3;

    float acc[4][4][4];
    #pragma unroll
    for (int i = 0; i < 4; i++)
        #pragma unroll
        for (int j = 0; j < 4; j++)
            #pragma unroll
            for (int e = 0; e < 4; e++) acc[i][j][e] = 0.f;

    int a_r = tid >> 3;
    int a_c = (tid & 7) * 4;
    int b_r = tid >> 5;
    int b_c = (tid & 31) * 4;

    for (int k0 = 0; k0 < K; k0 += 32) {
        #pragma unroll
        for (int i = 0; i < 4; i++) {
            float4 a = *(const float4*)(g_ctx + (size_t)(m0 + a_r + i * 32) * K + k0 + a_c);
            As[a_r + i * 32][a_c + 0] = f2tf(a.x);
            As[a_r + i * 32][a_c + 1] = f2tf(a.y);
            As[a_r + i * 32][a_c + 2] = f2tf(a.z);
            As[a_r + i * 32][a_c + 3] = f2tf(a.w);
            float4 b = *(const float4*)(W + (size_t)(k0 + b_r + i * 8) * N + n0 + b_c);
            Bs[b_r + i * 8][b_c + 0] = f2tf(b.x);
            Bs[b_r + i * 8][b_c + 1] = f2tf(b.y);
            Bs[b_r + i * 8][b_c + 2] = f2tf(b.z);
            Bs[b_r + i * 8][b_c + 3] = f2tf(b.w);
        }
        __syncthreads();
        #pragma unroll
        for (int kk = 0; kk < 4; kk++) {
            int kb = kk * 8;
            unsigned af[4][4], bf[4][2];
            #pragma unroll
            for (int i = 0; i < 4; i++) {
                int row = wm * 64 + i * 16 + g;
                af[i][0] = As[row][kb + tg];
                af[i][1] = As[row + 8][kb + tg];
                af[i][2] = As[row][kb + tg + 4];
                af[i][3] = As[row + 8][kb + tg + 4];
            }
            #pragma unroll
            for (int j = 0; j < 4; j++) {
                int col = wn * 32 + j * 8 + g;
                bf[j][0] = Bs[kb + tg][col];
                bf[j][1] = Bs[kb + tg + 4][col];
            }
            #pragma unroll
            for (int i = 0; i < 4; i++)
                #pragma unroll
                for (int j = 0; j < 4; j++)
                    mma8(acc[i][j], af[i][0], af[i][1], af[i][2], af[i][3],
                         bf[j][0], bf[j][1]);
        }
        __syncthreads();
    }

    #pragma unroll
    for (int i = 0; i < 4; i++)
        #pragma unroll
        for (int half = 0; half < 2; half++) {
            int m = m0 + wm * 64 + i * 16 + g + half * 8;
            #pragma unroll
            for (int j = 0; j < 4; j++) {
                int n = n0 + wn * 32 + j * 8 + 2 * tg;
                float2 v = make_float2(acc[i][j][half * 2 + 0] + bias[n],
                                       acc[i][j][half * 2 + 1] + bias[n + 1]);
                *(float2*)(out + (size_t)m * N + n) = v;
            }
        }
}

// ---------------------------------------------------------------------------
// Launch (graph-capturable, allocation-free).
// Inputs: query, mask(unused — causal is static), W_qkv, b_qkv, W_out, b_out.
// ---------------------------------------------------------------------------
extern "C" void kernel_launch(void* const* d_in, const int* in_sizes, int n_in,
                              void* d_out, int out_size)
{
    const float* query = (const float*)d_in[0];
    const float* W_qkv = (const float*)d_in[2];
    const float* b_qkv = (const float*)d_in[3];
    const float* W_out = (const float*)d_in[4];
    const float* b_out = (const float*)d_in[5];
    float* out = (float*)d_out;

    const int attn_smem = 3 * 64 * 68 * sizeof(float);   // 52224 bytes
    static int configured = 0;
    if (!configured) {
        cudaFuncSetAttribute(attn_kernel,
                             cudaFuncAttributeMaxDynamicSharedMemorySize, attn_smem);
        configured = 1;
    }

    qkv_gemm_kernel<<<dim3(N_QKV / 128, NM / 128), 256>>>(query, W_qkv, b_qkv);
    attn_kernel<<<dim3(NS / 64, NBH), 128, attn_smem>>>();
    out_gemm_kernel<<<dim3(ND / 128, NM / 128), 256>>>(W_out, b_out, out);
}

// round 5
// speedup vs baseline: 9.0909x; 1.0862x over previous
#include <cuda_runtime.h>
#include <cstdint>

// Problem dims
#define NB   4
#define NS   2048
#define ND   1024
#define NH   16
#define NDH  64
#define NBH  (NB * NH)     // 64
#define NM   (NB * NS)     // 8192 tokens
#define N_QKV (3 * ND)     // 3072
#define INV_SCALE 0.125f   // 1/sqrt(64)

// Scratch (static __device__ arrays: allocation-free per harness rules)
__device__ float g_Q[(size_t)NBH * NS * NDH];     // [bh][s][dh], tf32-rounded, pre-scaled
__device__ float g_K[(size_t)NBH * NS * NDH];
__device__ float g_V[(size_t)NBH * NS * NDH];
__device__ float g_ctx[(size_t)NM * ND];          // [b][s][d], tf32-rounded
__device__ float g_Aq[(size_t)NM * ND];           // query, tf32-rounded
__device__ float g_Wt_qkv[(size_t)N_QKV * ND];    // W_qkv^T [3072][1024], tf32-rounded
__device__ float g_Wt_out[(size_t)ND * ND];       // W_out^T [1024][1024], tf32-rounded

// ---------------------------------------------------------------------------
// helpers
// ---------------------------------------------------------------------------
__device__ __forceinline__ unsigned f2tf(float x) {
    unsigned u;
    asm("cvt.rna.tf32.f32 %0, %1;" : "=r"(u) : "f"(x));
    return u;
}

__device__ __forceinline__ uint32_t smem_u32(const void* p) {
    uint32_t a;
    asm("{ .reg .u64 t; cvta.to.shared.u64 t, %1; cvt.u32.u64 %0, t; }"
        : "=r"(a) : "l"(p));
    return a;
}

__device__ __forceinline__ void cp16(uint32_t dst, const void* src) {
    asm volatile("cp.async.cg.shared.global [%0], [%1], 16;"
                 :: "r"(dst), "l"(src) : "memory");
}
__device__ __forceinline__ void cp_commit() {
    asm volatile("cp.async.commit_group;" ::: "memory");
}
__device__ __forceinline__ void cp_wait1() {
    asm volatile("cp.async.wait_group 1;" ::: "memory");
}
__device__ __forceinline__ void cp_wait0() {
    asm volatile("cp.async.wait_group 0;" ::: "memory");
}

// m16n8k8 tf32 mma (SIMT tensor path — the only tensor path this toolchain exposes)
__device__ __forceinline__ void mma8(float* c,
                                     unsigned a0, unsigned a1, unsigned a2, unsigned a3,
                                     unsigned b0, unsigned b1) {
    asm volatile(
        "mma.sync.aligned.m16n8k8.row.col.f32.tf32.tf32.f32 "
        "{%0,%1,%2,%3},{%4,%5,%6,%7},{%8,%9},{%0,%1,%2,%3};"
        : "+f"(c[0]), "+f"(c[1]), "+f"(c[2]), "+f"(c[3])
        : "r"(a0), "r"(a1), "r"(a2), "r"(a3), "r"(b0), "r"(b1));
}

// ---------------------------------------------------------------------------
// Prepass: tf32-round a contiguous fp32 array (float4 granularity).
// ---------------------------------------------------------------------------
__global__ __launch_bounds__(256) void round_tf32_kernel(
    const float* __restrict__ src, float* __restrict__ dst)
{
    size_t i = ((size_t)blockIdx.x * 256 + threadIdx.x) * 4;
    float4 v = *(const float4*)(src + i);
    uint4 u;
    u.x = f2tf(v.x); u.y = f2tf(v.y); u.z = f2tf(v.z); u.w = f2tf(v.w);
    *(uint4*)(dst + i) = u;
}

// ---------------------------------------------------------------------------
// Transpose + tf32-round:  dst[C][R] = tf32(src[R][C])
// ---------------------------------------------------------------------------
__global__ __launch_bounds__(256) void transpose_tf32_kernel(
    const float* __restrict__ src, float* __restrict__ dst, int R, int C)
{
    __shared__ float t[32][33];
    int bx = blockIdx.x * 32;          // col base in src
    int by = blockIdx.y * 32;          // row base in src
    int tx = threadIdx.x & 31, ty = threadIdx.x >> 5;
    #pragma unroll
    for (int j = 0; j < 4; j++)
        t[ty + j * 8][tx] = src[(size_t)(by + ty + j * 8) * C + bx + tx];
    __syncthreads();
    #pragma unroll
    for (int j = 0; j < 4; j++)
        dst[(size_t)(bx + ty + j * 8) * R + by + tx] =
            __uint_as_float(f2tf(t[tx][ty + j * 8]));
}

// ---------------------------------------------------------------------------
// tf32 mma GEMM: C[M][N] = A[M][1024] @ Bt[N][1024]^T + bias.
// 128x128 block tile, BK=32, 2-stage cp.async double buffer, 256 threads,
// 8 warps in 2x4 grid (warp tile 64x32).  Both A and Bt tiles stored
// [128 rows][36-float stride] (k inner) — all fragment LDS conflict-free.
// MODE 0: QKV scatter epilogue.  MODE 1: out = acc + bias.
// ---------------------------------------------------------------------------
#define GSTR 36                           // smem row stride (floats)
#define GTILE (128 * GSTR)                // floats per tile buffer (4608)
#define GEMM_SMEM (4 * GTILE * 4)         // A0,A1,B0,B1 = 73728 bytes

template <int MODE>
__global__ __launch_bounds__(256) void mm_gemm_kernel(
    const float* __restrict__ A,
    const float* __restrict__ Bt,
    const float* __restrict__ bias,
    float* __restrict__ outp)
{
    extern __shared__ float sm[];
    float* Abuf[2] = { sm,             sm + GTILE };
    float* Bbuf[2] = { sm + 2 * GTILE, sm + 3 * GTILE };
    uint32_t sb = smem_u32(sm);

    int tid  = threadIdx.x;
    int warp = tid >> 5, lane = tid & 31;
    int wm   = warp >> 2, wn = warp & 3;      // 2 x 4 warp grid
    int g    = lane >> 2, tg = lane & 3;
    int m0   = blockIdx.y * 128;
    int n0   = blockIdx.x * 128;

    float acc[4][4][4];
    #pragma unroll
    for (int i = 0; i < 4; i++)
        #pragma unroll
        for (int j = 0; j < 4; j++)
            #pragma unroll
            for (int e = 0; e < 4; e++) acc[i][j][e] = 0.f;

    // loader: 1024 16B-chunks per tile, 4 per thread per tile
    // chunk ch: row = ch>>3, cc = ch&7  ->  src row*1024 + k0 + cc*4
    //                                      dst row*GSTR + cc*4
    auto prefetch = [&](int s, int buf) {
        int k0 = s * 32;
        uint32_t adst = sb + (uint32_t)((Abuf[buf] - sm) * 4);
        uint32_t bdst = sb + (uint32_t)((Bbuf[buf] - sm) * 4);
        #pragma unroll
        for (int i = 0; i < 4; i++) {
            int ch  = tid + i * 256;
            int row = ch >> 3, cc = ch & 7;
            uint32_t doff = (uint32_t)(row * GSTR + cc * 4) * 4u;
            cp16(adst + doff, A  + (size_t)(m0 + row) * 1024 + k0 + cc * 4);
            cp16(bdst + doff, Bt + (size_t)(n0 + row) * 1024 + k0 + cc * 4);
        }
        cp_commit();
    };

    prefetch(0, 0);
    prefetch(1, 1);

    for (int s = 0; s < 32; s++) {
        int buf = s & 1;
        if (s < 31) cp_wait1(); else cp_wait0();
        __syncthreads();

        const float* As = Abuf[buf];
        const float* Bs = Bbuf[buf];
        #pragma unroll
        for (int kk = 0; kk < 4; kk++) {
            int kb = kk * 8;
            unsigned af[4][4], bf[4][2];
            #pragma unroll
            for (int i = 0; i < 4; i++) {
                int row = wm * 64 + i * 16 + g;
                af[i][0] = __float_as_uint(As[row * GSTR + kb + tg]);
                af[i][1] = __float_as_uint(As[(row + 8) * GSTR + kb + tg]);
                af[i][2] = __float_as_uint(As[row * GSTR + kb + tg + 4]);
                af[i][3] = __float_as_uint(As[(row + 8) * GSTR + kb + tg + 4]);
            }
            #pragma unroll
            for (int j = 0; j < 4; j++) {
                int col = wn * 32 + j * 8 + g;
                bf[j][0] = __float_as_uint(Bs[col * GSTR + kb + tg]);
                bf[j][1] = __float_as_uint(Bs[col * GSTR + kb + tg + 4]);
            }
            #pragma unroll
            for (int i = 0; i < 4; i++)
                #pragma unroll
                for (int j = 0; j < 4; j++)
                    mma8(acc[i][j], af[i][0], af[i][1], af[i][2], af[i][3],
                         bf[j][0], bf[j][1]);
        }
        __syncthreads();                 // all reads done before buf is refilled
        if (s + 2 < 32) prefetch(s + 2, buf);
    }

    if (MODE == 0) {
        // scatter into Q/K/V.  n -> (h, dh, t) with n = h*192 + dh*3 + t.
        int hh[4][2], dd[4][2], tt[4][2];
        float bb[4][2];
        #pragma unroll
        for (int j = 0; j < 4; j++)
            #pragma unroll
            for (int e = 0; e < 2; e++) {
                int n = n0 + wn * 32 + j * 8 + 2 * tg + e;
                hh[j][e] = n / 192;
                int rem = n - hh[j][e] * 192;
                dd[j][e] = rem / 3;
                tt[j][e] = rem - dd[j][e] * 3;
                bb[j][e] = bias[n];
            }
        #pragma unroll
        for (int i = 0; i < 4; i++)
            #pragma unroll
            for (int half = 0; half < 2; half++) {
                int m  = m0 + wm * 64 + i * 16 + g + half * 8;
                int bi = m >> 11;
                int si = m & (NS - 1);
                #pragma unroll
                for (int j = 0; j < 4; j++)
                    #pragma unroll
                    for (int e = 0; e < 2; e++) {
                        float v = acc[i][j][half * 2 + e] + bb[j][e];
                        size_t idx = ((size_t)(bi * NH + hh[j][e]) * NS + si) * NDH + dd[j][e];
                        if (tt[j][e] == 0)      g_Q[idx] = __uint_as_float(f2tf(v * INV_SCALE));
                        else if (tt[j][e] == 1) g_K[idx] = __uint_as_float(f2tf(v));
                        else                    g_V[idx] = __uint_as_float(f2tf(v));
                    }
            }
    } else {
        #pragma unroll
        for (int i = 0; i < 4; i++)
            #pragma unroll
            for (int half = 0; half < 2; half++) {
                int m = m0 + wm * 64 + i * 16 + g + half * 8;
                #pragma unroll
                for (int j = 0; j < 4; j++) {
                    int n = n0 + wn * 32 + j * 8 + 2 * tg;
                    float2 v = make_float2(acc[i][j][half * 2 + 0] + bias[n],
                                           acc[i][j][half * 2 + 1] + bias[n + 1]);
                    *(float2*)(outp + (size_t)m * ND + n) = v;
                }
            }
    }
}

// ---------------------------------------------------------------------------
// Causal flash attention, tf32 mma, cp.async double-buffered K/V tiles.
// One block = (bh, 64-row q tile), 4 warps.  Separate P buffer (no aliasing).
// Strides: Q/K/P 68 (conflict-free), V 72 (conflict-free).
// ---------------------------------------------------------------------------
#define KSTR 68
#define VSTR 72
#define AQ_OFF 0
#define AK_OFF(b)  (64 * KSTR + (b) * 64 * KSTR)          // K0 @ 4352, K1 @ 8704
#define AV_OFF(b)  (3 * 64 * KSTR + (b) * 64 * VSTR)      // V0 @ 13056, V1 @ 17664
#define AP_OFF     (3 * 64 * KSTR + 2 * 64 * VSTR)        // P  @ 22272
#define ATTN_SMEM  ((AP_OFF + 64 * KSTR) * 4)             // 106496 bytes

__global__ __launch_bounds__(128) void attn_kernel()
{
    extern __shared__ float sm[];
    uint32_t sb = smem_u32(sm);
    float* Qs = sm + AQ_OFF;
    float* Ps = sm + AP_OFF;

    int tid  = threadIdx.x;
    int bh   = blockIdx.y;
    int qt   = blockIdx.x;
    int q0   = qt * 64;
    int warp = tid >> 5, lane = tid & 31;
    int g    = lane >> 2, tg = lane & 3;

    int r0 = warp * 16 + g;
    int r1 = r0 + 8;
    int qg0 = q0 + r0, qg1 = q0 + r1;

    const float* Kg = g_K + (size_t)bh * NS * NDH;
    const float* Vg = g_V + (size_t)bh * NS * NDH;

    // prefetch K/V tile kt into buffer b (1024 16B-chunks each, 8 per thread)
    auto prefetch = [&](int kt, int b) {
        const float* Ksrc = Kg + (size_t)kt * 64 * NDH;
        const float* Vsrc = Vg + (size_t)kt * 64 * NDH;
        uint32_t kdst = sb + AK_OFF(b) * 4;
        uint32_t vdst = sb + AV_OFF(b) * 4;
        #pragma unroll
        for (int i = 0; i < 8; i++) {
            int ch  = tid + i * 128;
            int row = ch >> 4, cc = ch & 15;
            cp16(kdst + (uint32_t)(row * KSTR + cc * 4) * 4u, Ksrc + row * 64 + cc * 4);
            cp16(vdst + (uint32_t)(row * VSTR + cc * 4) * 4u, Vsrc + row * 64 + cc * 4);
        }
        cp_commit();
    };

    prefetch(0, 0);

    // load Q tile (plain loads; overlaps with the cp.async above)
    const float* Qg = g_Q + ((size_t)bh * NS + q0) * NDH;
    #pragma unroll
    for (int it = 0; it < 8; it++) {
        int lin = tid + it * 128;
        int row = lin >> 4, col = (lin & 15) * 4;
        *(float4*)&Qs[row * KSTR + col] = *(const float4*)(Qg + (size_t)row * 64 + col);
    }

    float o[8][4];
    #pragma unroll
    for (int j = 0; j < 8; j++)
        #pragma unroll
        for (int e = 0; e < 4; e++) o[j][e] = 0.f;
    float m_run0 = -1e30f, m_run1 = -1e30f;
    float l_run0 = 0.f,    l_run1 = 0.f;

    for (int kt = 0; kt <= qt; kt++) {
        int buf = kt & 1;
        if (kt < qt) prefetch(kt + 1, buf ^ 1);
        if (kt < qt) cp_wait1(); else cp_wait0();
        __syncthreads();

        const float* Ks = sm + AK_OFF(buf);
        const float* Vs = sm + AV_OFF(buf);
        int k0 = kt * 64;

        // ---- S = Q @ K^T  (m16 x n64 per warp) ----
        float sc[8][4];
        #pragma unroll
        for (int j = 0; j < 8; j++)
            #pragma unroll
            for (int e = 0; e < 4; e++) sc[j][e] = 0.f;
        #pragma unroll
        for (int kk = 0; kk < 8; kk++) {
            int kb = kk * 8;
            unsigned a0 = __float_as_uint(Qs[r0 * KSTR + kb + tg]);
            unsigned a1 = __float_as_uint(Qs[r1 * KSTR + kb + tg]);
            unsigned a2 = __float_as_uint(Qs[r0 * KSTR + kb + tg + 4]);
            unsigned a3 = __float_as_uint(Qs[r1 * KSTR + kb + tg + 4]);
            #pragma unroll
            for (int j = 0; j < 8; j++) {
                unsigned b0 = __float_as_uint(Ks[(j * 8 + g) * KSTR + kb + tg]);
                unsigned b1 = __float_as_uint(Ks[(j * 8 + g) * KSTR + kb + tg + 4]);
                mma8(sc[j], a0, a1, a2, a3, b0, b1);
            }
        }

        // causal mask (diagonal tile only)
        if (kt == qt) {
            #pragma unroll
            for (int j = 0; j < 8; j++)
                #pragma unroll
                for (int e = 0; e < 2; e++) {
                    int kv = k0 + j * 8 + 2 * tg + e;
                    if (kv > qg0) sc[j][e]     = -1e30f;
                    if (kv > qg1) sc[j][2 + e] = -1e30f;
                }
        }

        // ---- online softmax ----
        float ml0 = -1e30f, ml1 = -1e30f;
        #pragma unroll
        for (int j = 0; j < 8; j++) {
            ml0 = fmaxf(ml0, fmaxf(sc[j][0], sc[j][1]));
            ml1 = fmaxf(ml1, fmaxf(sc[j][2], sc[j][3]));
        }
        ml0 = fmaxf(ml0, __shfl_xor_sync(0xffffffffu, ml0, 1));
        ml0 = fmaxf(ml0, __shfl_xor_sync(0xffffffffu, ml0, 2));
        ml1 = fmaxf(ml1, __shfl_xor_sync(0xffffffffu, ml1, 1));
        ml1 = fmaxf(ml1, __shfl_xor_sync(0xffffffffu, ml1, 2));
        float mn0 = fmaxf(m_run0, ml0);
        float mn1 = fmaxf(m_run1, ml1);
        float al0 = __expf(m_run0 - mn0);
        float al1 = __expf(m_run1 - mn1);
        float ls0 = 0.f, ls1 = 0.f;
        #pragma unroll
        for (int j = 0; j < 8; j++) {
            sc[j][0] = __expf(sc[j][0] - mn0);
            sc[j][1] = __expf(sc[j][1] - mn0);
            sc[j][2] = __expf(sc[j][2] - mn1);
            sc[j][3] = __expf(sc[j][3] - mn1);
            ls0 += sc[j][0] + sc[j][1];
            ls1 += sc[j][2] + sc[j][3];
        }
        ls0 += __shfl_xor_sync(0xffffffffu, ls0, 1);
        ls0 += __shfl_xor_sync(0xffffffffu, ls0, 2);
        ls1 += __shfl_xor_sync(0xffffffffu, ls1, 1);
        ls1 += __shfl_xor_sync(0xffffffffu, ls1, 2);
        l_run0 = l_run0 * al0 + ls0;
        l_run1 = l_run1 * al1 + ls1;
        m_run0 = mn0;
        m_run1 = mn1;
        #pragma unroll
        for (int j = 0; j < 8; j++) {
            o[j][0] *= al0;  o[j][1] *= al0;
            o[j][2] *= al1;  o[j][3] *= al1;
        }

        // write P (tf32-rounded) — separate buffer, no cross-warp hazard
        #pragma unroll
        for (int j = 0; j < 8; j++) {
            int cc = j * 8 + 2 * tg;
            *(float2*)&Ps[r0 * KSTR + cc] =
                make_float2(__uint_as_float(f2tf(sc[j][0])),
                            __uint_as_float(f2tf(sc[j][1])));
            *(float2*)&Ps[r1 * KSTR + cc] =
                make_float2(__uint_as_float(f2tf(sc[j][2])),
                            __uint_as_float(f2tf(sc[j][3])));
        }
        __syncwarp();      // each warp consumes only its own P rows

        // ---- O += P @ V  (m16 x n64 per warp) ----
        #pragma unroll
        for (int kk = 0; kk < 8; kk++) {
            int kb = kk * 8;
            unsigned a0 = __float_as_uint(Ps[r0 * KSTR + kb + tg]);
            unsigned a1 = __float_as_uint(Ps[r1 * KSTR + kb + tg]);
            unsigned a2 = __float_as_uint(Ps[r0 * KSTR + kb + tg + 4]);
            unsigned a3 = __float_as_uint(Ps[r1 * KSTR + kb + tg + 4]);
            #pragma unroll
            for (int j = 0; j < 8; j++) {
                unsigned b0 = __float_as_uint(Vs[(kb + tg) * VSTR + j * 8 + g]);
                unsigned b1 = __float_as_uint(Vs[(kb + tg + 4) * VSTR + j * 8 + g]);
                mma8(o[j], a0, a1, a2, a3, b0, b1);
            }
        }
        __syncthreads();   // K/V reads done before next prefetch overwrites
    }

    float inv0 = 1.f / l_run0;
    float inv1 = 1.f / l_run1;
    int bi = bh >> 4;
    int h  = bh & 15;
    float* d0 = g_ctx + ((size_t)(bi * NS) + qg0) * ND + h * NDH;
    float* d1 = g_ctx + ((size_t)(bi * NS) + qg1) * ND + h * NDH;
    #pragma unroll
    for (int j = 0; j < 8; j++) {
        int cc = j * 8 + 2 * tg;
        // tf32-rounded so the out-proj GEMM can consume it raw
        *(float2*)(d0 + cc) = make_float2(
            __uint_as_float(f2tf(o[j][0] * inv0)),
            __uint_as_float(f2tf(o[j][1] * inv0)));
        *(float2*)(d1 + cc) = make_float2(
            __uint_as_float(f2tf(o[j][2] * inv1)),
            __uint_as_float(f2tf(o[j][3] * inv1)));
    }
}

// ---------------------------------------------------------------------------
// Launch (graph-capturable, allocation-free).
// Inputs: query, mask(unused — causal is static), W_qkv, b_qkv, W_out, b_out.
// ---------------------------------------------------------------------------
extern "C" void kernel_launch(void* const* d_in, const int* in_sizes, int n_in,
                              void* d_out, int out_size)
{
    const float* query = (const float*)d_in[0];
    const float* W_qkv = (const float*)d_in[2];
    const float* b_qkv = (const float*)d_in[3];
    const float* W_out = (const float*)d_in[4];
    const float* b_out = (const float*)d_in[5];
    float* out = (float*)d_out;

    cudaFuncSetAttribute(attn_kernel,
                         cudaFuncAttributeMaxDynamicSharedMemorySize, ATTN_SMEM);
    cudaFuncSetAttribute(mm_gemm_kernel<0>,
                         cudaFuncAttributeMaxDynamicSharedMemorySize, GEMM_SMEM);
    cudaFuncSetAttribute(mm_gemm_kernel<1>,
                         cudaFuncAttributeMaxDynamicSharedMemorySize, GEMM_SMEM);

    float* Aq;      cudaGetSymbolAddress((void**)&Aq, g_Aq);
    float* Wt_qkv;  cudaGetSymbolAddress((void**)&Wt_qkv, g_Wt_qkv);
    float* Wt_out;  cudaGetSymbolAddress((void**)&Wt_out, g_Wt_out);
    float* ctx;     cudaGetSymbolAddress((void**)&ctx, g_ctx);

    // Prepasses: round A, transpose+round weights.
    round_tf32_kernel<<<(size_t)NM * ND / 1024, 256>>>(query, Aq);
    transpose_tf32_kernel<<<dim3(N_QKV / 32, ND / 32), 256>>>(W_qkv, Wt_qkv, ND, N_QKV);
    transpose_tf32_kernel<<<dim3(ND / 32, ND / 32), 256>>>(W_out, Wt_out, ND, ND);

    // QKV projection
    mm_gemm_kernel<0><<<dim3(N_QKV / 128, NM / 128), 256, GEMM_SMEM>>>(
        Aq, Wt_qkv, b_qkv, nullptr);

    // Attention
    attn_kernel<<<dim3(NS / 64, NBH), 128, ATTN_SMEM>>>();

    // Output projection
    mm_gemm_kernel<1><<<dim3(ND / 128, NM / 128), 256, GEMM_SMEM>>>(
        ctx, Wt_out, b_out, out);
}

// round 6
// speedup vs baseline: 15.1577x; 1.6673x over previous
#include <cuda_runtime.h>
#include <cuda_fp16.h>
#include <cstdint>

// Problem dims
#define NB   4
#define NS   2048
#define ND   1024
#define NH   16
#define NDH  64
#define NBH  (NB * NH)     // 64
#define NM   (NB * NS)     // 8192 tokens
#define N_QKV (3 * ND)     // 3072
#define INV_SCALE 0.125f   // 1/sqrt(64)

// Scratch (static __device__ arrays: allocation-free per harness rules)
__device__ __half g_Q[(size_t)NBH * NS * NDH];     // [bh][s][dh], pre-scaled
__device__ __half g_K[(size_t)NBH * NS * NDH];
__device__ __half g_V[(size_t)NBH * NS * NDH];
__device__ __half g_ctx[(size_t)NM * ND];          // [b][s][d]
__device__ __half g_Ah[(size_t)NM * ND];           // query, fp16
__device__ __half g_Wt_qkv[(size_t)N_QKV * ND];    // W_qkv^T [3072][1024] fp16
__device__ __half g_Wt_out[(size_t)ND * ND];       // W_out^T [1024][1024] fp16

// ---------------------------------------------------------------------------
// helpers
// ---------------------------------------------------------------------------
__device__ __forceinline__ uint32_t smem_u32(const void* p) {
    uint32_t a;
    asm("{ .reg .u64 t; cvta.to.shared.u64 t, %1; cvt.u32.u64 %0, t; }"
        : "=r"(a) : "l"(p));
    return a;
}
__device__ __forceinline__ void cp16(uint32_t dst, const void* src) {
    asm volatile("cp.async.cg.shared.global [%0], [%1], 16;"
                 :: "r"(dst), "l"(src) : "memory");
}
__device__ __forceinline__ void cp_commit() {
    asm volatile("cp.async.commit_group;" ::: "memory");
}
__device__ __forceinline__ void cp_wait1() {
    asm volatile("cp.async.wait_group 1;" ::: "memory");
}
__device__ __forceinline__ void cp_wait0() {
    asm volatile("cp.async.wait_group 0;" ::: "memory");
}

// fp16 m16n8k16 mma, fp32 accumulate
__device__ __forceinline__ void mma16(float* c,
                                      unsigned a0, unsigned a1, unsigned a2, unsigned a3,
                                      unsigned b0, unsigned b1) {
    asm volatile(
        "mma.sync.aligned.m16n8k16.row.col.f32.f16.f16.f32 "
        "{%0,%1,%2,%3},{%4,%5,%6,%7},{%8,%9},{%0,%1,%2,%3};"
        : "+f"(c[0]), "+f"(c[1]), "+f"(c[2]), "+f"(c[3])
        : "r"(a0), "r"(a1), "r"(a2), "r"(a3), "r"(b0), "r"(b1));
}

__device__ __forceinline__ void ldm4(unsigned& r0, unsigned& r1, unsigned& r2,
                                     unsigned& r3, uint32_t addr) {
    asm volatile("ldmatrix.sync.aligned.m8n8.x4.shared.b16 {%0,%1,%2,%3}, [%4];"
                 : "=r"(r0), "=r"(r1), "=r"(r2), "=r"(r3) : "r"(addr));
}
__device__ __forceinline__ void ldm4t(unsigned& r0, unsigned& r1, unsigned& r2,
                                      unsigned& r3, uint32_t addr) {
    asm volatile("ldmatrix.sync.aligned.m8n8.x4.trans.shared.b16 {%0,%1,%2,%3}, [%4];"
                 : "=r"(r0), "=r"(r1), "=r"(r2), "=r"(r3) : "r"(addr));
}

// ---------------------------------------------------------------------------
// Prepass: fp32 -> fp16 (4 elements/thread)
// ---------------------------------------------------------------------------
__global__ __launch_bounds__(256) void round_h_kernel(
    const float* __restrict__ src, __half* __restrict__ dst)
{
    size_t i = ((size_t)blockIdx.x * 256 + threadIdx.x) * 4;
    float4 v = *(const float4*)(src + i);
    __half2 h0 = __floats2half2_rn(v.x, v.y);
    __half2 h1 = __floats2half2_rn(v.z, v.w);
    *(__half2*)(dst + i)     = h0;
    *(__half2*)(dst + i + 2) = h1;
}

// ---------------------------------------------------------------------------
// Transpose + fp16 convert:  dst[C][R] = h(src[R][C])
// ---------------------------------------------------------------------------
__global__ __launch_bounds__(256) void transpose_h_kernel(
    const float* __restrict__ src, __half* __restrict__ dst, int R, int C)
{
    __shared__ float t[32][33];
    int bx = blockIdx.x * 32;
    int by = blockIdx.y * 32;
    int tx = threadIdx.x & 31, ty = threadIdx.x >> 5;
    #pragma unroll
    for (int j = 0; j < 4; j++)
        t[ty + j * 8][tx] = src[(size_t)(by + ty + j * 8) * C + bx + tx];
    __syncthreads();
    #pragma unroll
    for (int j = 0; j < 4; j++)
        dst[(size_t)(bx + ty + j * 8) * R + by + tx] =
            __float2half_rn(t[tx][ty + j * 8]);
}

// ---------------------------------------------------------------------------
// fp16 mma GEMM: C[M][N] = A[M][1024] @ Bt[N][1024]^T + bias (fp32 accum).
// 128x128 block tile, BK=64 halfs, 2-stage cp.async double buffer, 256 thr,
// 8 warps in 2x4 grid (warp tile 64x32).  Tiles [128 rows][72-half stride],
// k-contiguous; ldmatrix conflict-free (144B row offset -> 4r mod 32 banks).
// MODE 0: QKV scatter epilogue (fp16 out).  MODE 1: fp32 out = acc + bias.
// ---------------------------------------------------------------------------
#define GS   72                           // smem row stride (halfs)
#define GT   (128 * GS)                   // halfs per tile (9216)
#define GEMM_SMEM (4 * GT * 2)            // A0,A1,B0,B1 = 73728 bytes

template <int MODE>
__global__ __launch_bounds__(256) void mm_gemm_kernel(
    const __half* __restrict__ A,
    const __half* __restrict__ Bt,
    const float* __restrict__ bias,
    float* __restrict__ outp)
{
    extern __shared__ __half hsm[];
    uint32_t sb = smem_u32(hsm);
    const uint32_t Aoff[2] = { 0u, (uint32_t)GT * 2u };
    const uint32_t Boff[2] = { (uint32_t)GT * 4u, (uint32_t)GT * 6u };

    int tid  = threadIdx.x;
    int warp = tid >> 5, lane = tid & 31;
    int wm   = warp >> 2, wn = warp & 3;      // 2 x 4 warp grid
    int g    = lane >> 2, tg = lane & 3;
    int m0   = blockIdx.y * 128;
    int n0   = blockIdx.x * 128;

    // ldmatrix lane addressing offsets
    int lrow = lane & 15;                 // row within 16-row group
    int lcol = (lane >> 4) * 8;           // 0 or 8 halfs

    float acc[4][4][4];
    #pragma unroll
    for (int i = 0; i < 4; i++)
        #pragma unroll
        for (int j = 0; j < 4; j++)
            #pragma unroll
            for (int e = 0; e < 4; e++) acc[i][j][e] = 0.f;

    // loader: per tile 128 rows x 8 chunks(16B) = 1024 chunks; A+B = 2048; 8/thread
    auto prefetch = [&](int s, int buf) {
        int k0 = s * 64;
        #pragma unroll
        for (int i = 0; i < 4; i++) {
            int ch  = tid + i * 256;              // 0..1023  (A)
            int row = ch >> 3, q = ch & 7;
            uint32_t doff = (uint32_t)(row * GS + q * 8) * 2u;
            cp16(sb + Aoff[buf] + doff, A  + (size_t)(m0 + row) * 1024 + k0 + q * 8);
            cp16(sb + Boff[buf] + doff, Bt + (size_t)(n0 + row) * 1024 + k0 + q * 8);
        }
        cp_commit();
    };

    prefetch(0, 0);
    prefetch(1, 1);

    for (int s = 0; s < 16; s++) {
        int buf = s & 1;
        if (s < 15) cp_wait1(); else cp_wait0();
        __syncthreads();

        uint32_t Ab = sb + Aoff[buf];
        uint32_t Bb = sb + Boff[buf];
        #pragma unroll
        for (int kk = 0; kk < 4; kk++) {
            int kb = kk * 16;
            unsigned af[4][4], bf[4][2];
            #pragma unroll
            for (int i = 0; i < 4; i++) {
                uint32_t addr = Ab + (uint32_t)((wm * 64 + i * 16 + lrow) * GS + kb + lcol) * 2u;
                ldm4(af[i][0], af[i][1], af[i][2], af[i][3], addr);
            }
            #pragma unroll
            for (int nt = 0; nt < 2; nt++) {
                unsigned r0, r1, r2, r3;
                uint32_t addr = Bb + (uint32_t)((wn * 32 + nt * 16 + lrow) * GS + kb + lcol) * 2u;
                ldm4(r0, r1, r2, r3, addr);
                bf[nt * 2][0] = r0;  bf[nt * 2 + 1][0] = r1;
                bf[nt * 2][1] = r2;  bf[nt * 2 + 1][1] = r3;
            }
            #pragma unroll
            for (int i = 0; i < 4; i++)
                #pragma unroll
                for (int j = 0; j < 4; j++)
                    mma16(acc[i][j], af[i][0], af[i][1], af[i][2], af[i][3],
                          bf[j][0], bf[j][1]);
        }
        __syncthreads();                 // reads done before buf is refilled
        if (s + 2 < 16) prefetch(s + 2, buf);
    }

    if (MODE == 0) {
        // scatter into Q/K/V.  n -> (h, dh, t) with n = h*192 + dh*3 + t.
        int hh[4][2], dd[4][2], tt[4][2];
        float bb[4][2];
        #pragma unroll
        for (int j = 0; j < 4; j++)
            #pragma unroll
            for (int e = 0; e < 2; e++) {
                int n = n0 + wn * 32 + j * 8 + 2 * tg + e;
                hh[j][e] = n / 192;
                int rem = n - hh[j][e] * 192;
                dd[j][e] = rem / 3;
                tt[j][e] = rem - dd[j][e] * 3;
                bb[j][e] = bias[n];
            }
        #pragma unroll
        for (int i = 0; i < 4; i++)
            #pragma unroll
            for (int half = 0; half < 2; half++) {
                int m  = m0 + wm * 64 + i * 16 + g + half * 8;
                int bi = m >> 11;
                int si = m & (NS - 1);
                #pragma unroll
                for (int j = 0; j < 4; j++)
                    #pragma unroll
                    for (int e = 0; e < 2; e++) {
                        float v = acc[i][j][half * 2 + e] + bb[j][e];
                        size_t idx = ((size_t)(bi * NH + hh[j][e]) * NS + si) * NDH + dd[j][e];
                        if (tt[j][e] == 0)      g_Q[idx] = __float2half_rn(v * INV_SCALE);
                        else if (tt[j][e] == 1) g_K[idx] = __float2half_rn(v);
                        else                    g_V[idx] = __float2half_rn(v);
                    }
            }
    } else {
        #pragma unroll
        for (int i = 0; i < 4; i++)
            #pragma unroll
            for (int half = 0; half < 2; half++) {
                int m = m0 + wm * 64 + i * 16 + g + half * 8;
                #pragma unroll
                for (int j = 0; j < 4; j++) {
                    int n = n0 + wn * 32 + j * 8 + 2 * tg;
                    float2 v = make_float2(acc[i][j][half * 2 + 0] + bias[n],
                                           acc[i][j][half * 2 + 1] + bias[n + 1]);
                    *(float2*)(outp + (size_t)m * ND + n) = v;
                }
            }
    }
}

// ---------------------------------------------------------------------------
// Causal flash attention, fp16 mma + ldmatrix, cp.async double-buffered K/V.
// One block = (bh, 64-row q tile), 4 warps (warp w: q rows 16w..16w+15).
// All tiles [64 rows][72-half stride].  P separate buffer.  fp32 softmax/acc.
// ---------------------------------------------------------------------------
#define ASTR 72
#define AT   (64 * ASTR)                      // halfs per tile (4608)
#define AQ_OFF 0
#define AK_OFF(b)  (AT + (b) * AT)            // K0, K1
#define AV_OFF(b)  (3 * AT + (b) * AT)        // V0, V1
#define AP_OFF     (5 * AT)                   // P
#define ATTN_SMEM  (6 * AT * 2)               // 55296 bytes

__global__ __launch_bounds__(128) void attn_kernel()
{
    extern __shared__ __half asm_[];
    uint32_t sb = smem_u32(asm_);
    __half* Qs = asm_ + AQ_OFF;
    __half* Ps = asm_ + AP_OFF;

    int tid  = threadIdx.x;
    int bh   = blockIdx.y;
    int qt   = blockIdx.x;
    int q0   = qt * 64;
    int warp = tid >> 5, lane = tid & 31;
    int g    = lane >> 2, tg = lane & 3;
    int lrow = lane & 15;
    int lcol = (lane >> 4) * 8;

    int r0 = warp * 16 + g;
    int r1 = r0 + 8;
    int qg0 = q0 + r0, qg1 = q0 + r1;

    const __half* Kg = g_K + (size_t)bh * NS * NDH;
    const __half* Vg = g_V + (size_t)bh * NS * NDH;

    // prefetch K/V tile kt into buffer b: 2 x 512 chunks(16B), 8 per thread
    auto prefetch = [&](int kt, int b) {
        const __half* Ksrc = Kg + (size_t)kt * 64 * NDH;
        const __half* Vsrc = Vg + (size_t)kt * 64 * NDH;
        uint32_t kdst = sb + AK_OFF(b) * 2;
        uint32_t vdst = sb + AV_OFF(b) * 2;
        #pragma unroll
        for (int i = 0; i < 4; i++) {
            int ch  = tid + i * 128;           // 0..511
            int row = ch >> 3, q = ch & 7;
            uint32_t doff = (uint32_t)(row * ASTR + q * 8) * 2u;
            cp16(kdst + doff, Ksrc + row * 64 + q * 8);
            cp16(vdst + doff, Vsrc + row * 64 + q * 8);
        }
        cp_commit();
    };

    prefetch(0, 0);

    // load Q tile (plain loads; overlaps with cp.async above)
    const __half* Qg = g_Q + ((size_t)bh * NS + q0) * NDH;
    #pragma unroll
    for (int it = 0; it < 4; it++) {
        int ch  = tid + it * 128;
        int row = ch >> 3, q = ch & 7;
        *(uint4*)&Qs[row * ASTR + q * 8] = *(const uint4*)(Qg + (size_t)row * 64 + q * 8);
    }

    float o[8][4];
    #pragma unroll
    for (int j = 0; j < 8; j++)
        #pragma unroll
        for (int e = 0; e < 4; e++) o[j][e] = 0.f;
    float m_run0 = -1e30f, m_run1 = -1e30f;
    float l_run0 = 0.f,    l_run1 = 0.f;

    for (int kt = 0; kt <= qt; kt++) {
        int buf = kt & 1;
        if (kt < qt) prefetch(kt + 1, buf ^ 1);
        if (kt < qt) cp_wait1(); else cp_wait0();
        __syncthreads();

        uint32_t Kb = sb + AK_OFF(buf) * 2;
        uint32_t Vb = sb + AV_OFF(buf) * 2;
        int k0 = kt * 64;

        // ---- S = Q @ K^T  (m16 x n64 per warp, 4 k16 steps) ----
        float sc[8][4];
        #pragma unroll
        for (int j = 0; j < 8; j++)
            #pragma unroll
            for (int e = 0; e < 4; e++) sc[j][e] = 0.f;
        #pragma unroll
        for (int kk = 0; kk < 4; kk++) {
            int kb = kk * 16;
            unsigned a0, a1, a2, a3;
            ldm4(a0, a1, a2, a3,
                 sb + (uint32_t)((warp * 16 + lrow) * ASTR + kb + lcol) * 2u);
            #pragma unroll
            for (int nt = 0; nt < 4; nt++) {
                unsigned r0q, r1q, r2q, r3q;
                ldm4(r0q, r1q, r2q, r3q,
                     Kb + (uint32_t)((nt * 16 + lrow) * ASTR + kb + lcol) * 2u);
                mma16(sc[nt * 2],     a0, a1, a2, a3, r0q, r2q);
                mma16(sc[nt * 2 + 1], a0, a1, a2, a3, r1q, r3q);
            }
        }

        // causal mask (diagonal tile only)
        if (kt == qt) {
            #pragma unroll
            for (int j = 0; j < 8; j++)
                #pragma unroll
                for (int e = 0; e < 2; e++) {
                    int kv = k0 + j * 8 + 2 * tg + e;
                    if (kv > qg0) sc[j][e]     = -1e30f;
                    if (kv > qg1) sc[j][2 + e] = -1e30f;
                }
        }

        // ---- online softmax ----
        float ml0 = -1e30f, ml1 = -1e30f;
        #pragma unroll
        for (int j = 0; j < 8; j++) {
            ml0 = fmaxf(ml0, fmaxf(sc[j][0], sc[j][1]));
            ml1 = fmaxf(ml1, fmaxf(sc[j][2], sc[j][3]));
        }
        ml0 = fmaxf(ml0, __shfl_xor_sync(0xffffffffu, ml0, 1));
        ml0 = fmaxf(ml0, __shfl_xor_sync(0xffffffffu, ml0, 2));
        ml1 = fmaxf(ml1, __shfl_xor_sync(0xffffffffu, ml1, 1));
        ml1 = fmaxf(ml1, __shfl_xor_sync(0xffffffffu, ml1, 2));
        float mn0 = fmaxf(m_run0, ml0);
        float mn1 = fmaxf(m_run1, ml1);
        float al0 = __expf(m_run0 - mn0);
        float al1 = __expf(m_run1 - mn1);
        float ls0 = 0.f, ls1 = 0.f;
        #pragma unroll
        for (int j = 0; j < 8; j++) {
            sc[j][0] = __expf(sc[j][0] - mn0);
            sc[j][1] = __expf(sc[j][1] - mn0);
            sc[j][2] = __expf(sc[j][2] - mn1);
            sc[j][3] = __expf(sc[j][3] - mn1);
            ls0 += sc[j][0] + sc[j][1];
            ls1 += sc[j][2] + sc[j][3];
        }
        ls0 += __shfl_xor_sync(0xffffffffu, ls0, 1);
        ls0 += __shfl_xor_sync(0xffffffffu, ls0, 2);
        ls1 += __shfl_xor_sync(0xffffffffu, ls1, 1);
        ls1 += __shfl_xor_sync(0xffffffffu, ls1, 2);
        l_run0 = l_run0 * al0 + ls0;
        l_run1 = l_run1 * al1 + ls1;
        m_run0 = mn0;
        m_run1 = mn1;
        #pragma unroll
        for (int j = 0; j < 8; j++) {
            o[j][0] *= al0;  o[j][1] *= al0;
            o[j][2] *= al1;  o[j][3] *= al1;
        }

        // write P (fp16) — separate buffer, each warp owns its rows
        #pragma unroll
        for (int j = 0; j < 8; j++) {
            int cc = j * 8 + 2 * tg;
            *(__half2*)&Ps[r0 * ASTR + cc] = __floats2half2_rn(sc[j][0], sc[j][1]);
            *(__half2*)&Ps[r1 * ASTR + cc] = __floats2half2_rn(sc[j][2], sc[j][3]);
        }
        __syncwarp();

        // ---- O += P @ V  (m16 x n64 per warp, 4 k16 steps, V via trans) ----
        #pragma unroll
        for (int kk = 0; kk < 4; kk++) {
            int kb = kk * 16;
            unsigned a0, a1, a2, a3;
            ldm4(a0, a1, a2, a3,
                 sb + (uint32_t)(AP_OFF * 2) +
                     (uint32_t)((warp * 16 + lrow) * ASTR + kb + lcol) * 2u);
            #pragma unroll
            for (int nt = 0; nt < 4; nt++) {
                unsigned r0q, r1q, r2q, r3q;
                ldm4t(r0q, r1q, r2q, r3q,
                      Vb + (uint32_t)((kb + lrow) * ASTR + nt * 16 + lcol) * 2u);
                mma16(o[nt * 2],     a0, a1, a2, a3, r0q, r1q);
                mma16(o[nt * 2 + 1], a0, a1, a2, a3, r2q, r3q);
            }
        }
        __syncthreads();   // K/V reads done before next prefetch overwrites
    }

    float inv0 = 1.f / l_run0;
    float inv1 = 1.f / l_run1;
    int bi = bh >> 4;
    int h  = bh & 15;
    __half* d0 = g_ctx + ((size_t)(bi * NS) + qg0) * ND + h * NDH;
    __half* d1 = g_ctx + ((size_t)(bi * NS) + qg1) * ND + h * NDH;
    #pragma unroll
    for (int j = 0; j < 8; j++) {
        int cc = j * 8 + 2 * tg;
        *(__half2*)(d0 + cc) = __floats2half2_rn(o[j][0] * inv0, o[j][1] * inv0);
        *(__half2*)(d1 + cc) = __floats2half2_rn(o[j][2] * inv1, o[j][3] * inv1);
    }
}

// ---------------------------------------------------------------------------
// Launch (graph-capturable, allocation-free).
// Inputs: query, mask(unused — causal is static), W_qkv, b_qkv, W_out, b_out.
// ---------------------------------------------------------------------------
extern "C" void kernel_launch(void* const* d_in, const int* in_sizes, int n_in,
                              void* d_out, int out_size)
{
    const float* query = (const float*)d_in[0];
    const float* W_qkv = (const float*)d_in[2];
    const float* b_qkv = (const float*)d_in[3];
    const float* W_out = (const float*)d_in[4];
    const float* b_out = (const float*)d_in[5];
    float* out = (float*)d_out;

    cudaFuncSetAttribute(attn_kernel,
                         cudaFuncAttributeMaxDynamicSharedMemorySize, ATTN_SMEM);
    cudaFuncSetAttribute(mm_gemm_kernel<0>,
                         cudaFuncAttributeMaxDynamicSharedMemorySize, GEMM_SMEM);
    cudaFuncSetAttribute(mm_gemm_kernel<1>,
                         cudaFuncAttributeMaxDynamicSharedMemorySize, GEMM_SMEM);

    __half* Ah;      cudaGetSymbolAddress((void**)&Ah, g_Ah);
    __half* Wt_qkv;  cudaGetSymbolAddress((void**)&Wt_qkv, g_Wt_qkv);
    __half* Wt_out;  cudaGetSymbolAddress((void**)&Wt_out, g_Wt_out);
    __half* ctx;     cudaGetSymbolAddress((void**)&ctx, g_ctx);

    // Prepasses: convert A, transpose+convert weights.
    round_h_kernel<<<(size_t)NM * ND / 1024, 256>>>(query, Ah);
    transpose_h_kernel<<<dim3(N_QKV / 32, ND / 32), 256>>>(W_qkv, Wt_qkv, ND, N_QKV);
    transpose_h_kernel<<<dim3(ND / 32, ND / 32), 256>>>(W_out, Wt_out, ND, ND);

    // QKV projection
    mm_gemm_kernel<0><<<dim3(N_QKV / 128, NM / 128), 256, GEMM_SMEM>>>(
        Ah, Wt_qkv, b_qkv, nullptr);

    // Attention
    attn_kernel<<<dim3(NS / 64, NBH), 128, ATTN_SMEM>>>();

    // Output projection
    mm_gemm_kernel<1><<<dim3(ND / 128, NM / 128), 256, GEMM_SMEM>>>(
        ctx, Wt_out, b_out, out);
}

// round 7
// speedup vs baseline: 15.4418x; 1.0187x over previous
#include <cuda_runtime.h>
#include <cuda_fp16.h>
#include <cstdint>

// Problem dims
#define NB   4
#define NS   2048
#define ND   1024
#define NH   16
#define NDH  64
#define NBH  (NB * NH)     // 64
#define NM   (NB * NS)     // 8192 tokens
#define N_QKV (3 * ND)     // 3072
#define INV_SCALE 0.125f   // 1/sqrt(64)

// Scratch (static __device__ arrays: allocation-free per harness rules)
__device__ __half g_Q[(size_t)NBH * NS * NDH];     // [bh][s][dh], pre-scaled
__device__ __half g_K[(size_t)NBH * NS * NDH];
__device__ __half g_V[(size_t)NBH * NS * NDH];
__device__ __half g_ctx[(size_t)NM * ND];          // [b][s][d]
__device__ __half g_Ah[(size_t)NM * ND];           // query, fp16
__device__ __half g_Wt_qkv[(size_t)N_QKV * ND];    // W_qkv^T [3072][1024] fp16
__device__ __half g_Wt_out[(size_t)ND * ND];       // W_out^T [1024][1024] fp16

// ---------------------------------------------------------------------------
// helpers
// ---------------------------------------------------------------------------
__device__ __forceinline__ uint32_t smem_u32(const void* p) {
    uint32_t a;
    asm("{ .reg .u64 t; cvta.to.shared.u64 t, %1; cvt.u32.u64 %0, t; }"
        : "=r"(a) : "l"(p));
    return a;
}
__device__ __forceinline__ void cp16(uint32_t dst, const void* src) {
    asm volatile("cp.async.cg.shared.global [%0], [%1], 16;"
                 :: "r"(dst), "l"(src) : "memory");
}
__device__ __forceinline__ void cp_commit() {
    asm volatile("cp.async.commit_group;" ::: "memory");
}
template <int N>
__device__ __forceinline__ void cp_wait() {
    asm volatile("cp.async.wait_group %0;" :: "n"(N) : "memory");
}

// fp16 m16n8k16 mma, fp32 accumulate
__device__ __forceinline__ void mma16(float* c,
                                      unsigned a0, unsigned a1, unsigned a2, unsigned a3,
                                      unsigned b0, unsigned b1) {
    asm volatile(
        "mma.sync.aligned.m16n8k16.row.col.f32.f16.f16.f32 "
        "{%0,%1,%2,%3},{%4,%5,%6,%7},{%8,%9},{%0,%1,%2,%3};"
        : "+f"(c[0]), "+f"(c[1]), "+f"(c[2]), "+f"(c[3])
        : "r"(a0), "r"(a1), "r"(a2), "r"(a3), "r"(b0), "r"(b1));
}

__device__ __forceinline__ void ldm4(unsigned& r0, unsigned& r1, unsigned& r2,
                                     unsigned& r3, uint32_t addr) {
    asm volatile("ldmatrix.sync.aligned.m8n8.x4.shared.b16 {%0,%1,%2,%3}, [%4];"
                 : "=r"(r0), "=r"(r1), "=r"(r2), "=r"(r3) : "r"(addr));
}
__device__ __forceinline__ void ldm4t(unsigned& r0, unsigned& r1, unsigned& r2,
                                      unsigned& r3, uint32_t addr) {
    asm volatile("ldmatrix.sync.aligned.m8n8.x4.trans.shared.b16 {%0,%1,%2,%3}, [%4];"
                 : "=r"(r0), "=r"(r1), "=r"(r2), "=r"(r3) : "r"(addr));
}

// ---------------------------------------------------------------------------
// Prepass: fp32 -> fp16 (4 elements/thread)
// ---------------------------------------------------------------------------
__global__ __launch_bounds__(256) void round_h_kernel(
    const float* __restrict__ src, __half* __restrict__ dst)
{
    size_t i = ((size_t)blockIdx.x * 256 + threadIdx.x) * 4;
    float4 v = *(const float4*)(src + i);
    *(__half2*)(dst + i)     = __floats2half2_rn(v.x, v.y);
    *(__half2*)(dst + i + 2) = __floats2half2_rn(v.z, v.w);
}

// ---------------------------------------------------------------------------
// Transpose + fp16 convert:  dst[C][R] = h(src[R][C])
// ---------------------------------------------------------------------------
__global__ __launch_bounds__(256) void transpose_h_kernel(
    const float* __restrict__ src, __half* __restrict__ dst, int R, int C)
{
    __shared__ float t[32][33];
    int bx = blockIdx.x * 32;
    int by = blockIdx.y * 32;
    int tx = threadIdx.x & 31, ty = threadIdx.x >> 5;
    #pragma unroll
    for (int j = 0; j < 4; j++)
        t[ty + j * 8][tx] = src[(size_t)(by + ty + j * 8) * C + bx + tx];
    __syncthreads();
    #pragma unroll
    for (int j = 0; j < 4; j++)
        dst[(size_t)(bx + ty + j * 8) * R + by + tx] =
            __float2half_rn(t[tx][ty + j * 8]);
}

// ---------------------------------------------------------------------------
// fp16 mma GEMM: C[M][N] = A[M][1024] @ Bt[N][1024]^T + bias (fp32 accum).
// Block tile 128x128, BK=64 halfs, 3-stage cp.async pipeline, ONE sync/stage.
// 4 warps (128 threads), warp tile 64x64 (2x2 warp grid): 32 ldmatrix feed
// 128 mma per stage per warp.  Tiles [128 rows][72-half stride], k-contiguous;
// ldmatrix conflict-free (144B rows -> 4r mod 32 banks).
// MODE 0: QKV scatter epilogue (fp16 out).  MODE 1: fp32 out = acc + bias.
// ---------------------------------------------------------------------------
#define GS    72                          // smem row stride (halfs)
#define GT    (128 * GS)                  // halfs per tile (9216)
#define GSTG  (2 * GT)                    // halfs per stage (A + B)
#define GEMM_SMEM (3 * GSTG * 2)          // 110592 bytes

template <int MODE>
__global__ __launch_bounds__(128) void mm_gemm_kernel(
    const __half* __restrict__ A,
    const __half* __restrict__ Bt,
    const float* __restrict__ bias,
    float* __restrict__ outp)
{
    extern __shared__ __half hsm[];
    uint32_t sb = smem_u32(hsm);

    int tid  = threadIdx.x;
    int warp = tid >> 5, lane = tid & 31;
    int wm   = warp >> 1, wn = warp & 1;      // 2 x 2 warp grid, tile 64x64
    int g    = lane >> 2, tg = lane & 3;
    int m0   = blockIdx.y * 128;
    int n0   = blockIdx.x * 128;

    int lrow = lane & 15;                 // ldmatrix row
    int lcol = (lane >> 4) * 8;           // ldmatrix col half-offset

    float acc[4][8][4];
    #pragma unroll
    for (int i = 0; i < 4; i++)
        #pragma unroll
        for (int j = 0; j < 8; j++)
            #pragma unroll
            for (int e = 0; e < 4; e++) acc[i][j][e] = 0.f;

    // loader: per stage, A tile 1024 chunks(16B) + B tile 1024; 16 per thread
    auto prefetch = [&](int t) {
        int st = t % 3;
        int k0 = t * 64;
        uint32_t abase = sb + (uint32_t)(st * GSTG) * 2u;
        uint32_t bbase = abase + (uint32_t)GT * 2u;
        #pragma unroll
        for (int i = 0; i < 8; i++) {
            int ch  = tid + i * 128;              // 0..1023
            int row = ch >> 3, q = ch & 7;
            uint32_t doff = (uint32_t)(row * GS + q * 8) * 2u;
            cp16(abase + doff, A  + (size_t)(m0 + row) * 1024 + k0 + q * 8);
            cp16(bbase + doff, Bt + (size_t)(n0 + row) * 1024 + k0 + q * 8);
        }
        cp_commit();
    };

    prefetch(0);
    prefetch(1);

    for (int s = 0; s < 16; s++) {
        if (s < 15) cp_wait<1>(); else cp_wait<0>();
        __syncthreads();                  // tile s visible; stage (s-1)%3 free
        if (s + 2 < 16) prefetch(s + 2);  // into stage (s+2)%3 == (s-1)%3

        uint32_t Ab = sb + (uint32_t)((s % 3) * GSTG) * 2u;
        uint32_t Bb = Ab + (uint32_t)GT * 2u;
        #pragma unroll
        for (int kk = 0; kk < 4; kk++) {
            int kb = kk * 16;
            unsigned af[4][4], bf[8][2];
            #pragma unroll
            for (int i = 0; i < 4; i++) {
                uint32_t addr = Ab + (uint32_t)((wm * 64 + i * 16 + lrow) * GS + kb + lcol) * 2u;
                ldm4(af[i][0], af[i][1], af[i][2], af[i][3], addr);
            }
            #pragma unroll
            for (int nt = 0; nt < 4; nt++) {
                unsigned r0, r1, r2, r3;
                uint32_t addr = Bb + (uint32_t)((wn * 64 + nt * 16 + lrow) * GS + kb + lcol) * 2u;
                ldm4(r0, r1, r2, r3, addr);
                bf[nt * 2][0] = r0;  bf[nt * 2 + 1][0] = r1;
                bf[nt * 2][1] = r2;  bf[nt * 2 + 1][1] = r3;
            }
            #pragma unroll
            for (int i = 0; i < 4; i++)
                #pragma unroll
                for (int j = 0; j < 8; j++)
                    mma16(acc[i][j], af[i][0], af[i][1], af[i][2], af[i][3],
                          bf[j][0], bf[j][1]);
        }
    }

    if (MODE == 0) {
        // scatter into Q/K/V.  n -> (h, dh, t) with n = h*192 + dh*3 + t.
        int hh[8][2], dd[8][2], tt[8][2];
        float bb[8][2];
        #pragma unroll
        for (int j = 0; j < 8; j++)
            #pragma unroll
            for (int e = 0; e < 2; e++) {
                int n = n0 + wn * 64 + j * 8 + 2 * tg + e;
                hh[j][e] = n / 192;
                int rem = n - hh[j][e] * 192;
                dd[j][e] = rem / 3;
                tt[j][e] = rem - dd[j][e] * 3;
                bb[j][e] = bias[n];
            }
        #pragma unroll
        for (int i = 0; i < 4; i++)
            #pragma unroll
            for (int half = 0; half < 2; half++) {
                int m  = m0 + wm * 64 + i * 16 + g + half * 8;
                int bi = m >> 11;
                int si = m & (NS - 1);
                #pragma unroll
                for (int j = 0; j < 8; j++)
                    #pragma unroll
                    for (int e = 0; e < 2; e++) {
                        float v = acc[i][j][half * 2 + e] + bb[j][e];
                        size_t idx = ((size_t)(bi * NH + hh[j][e]) * NS + si) * NDH + dd[j][e];
                        if (tt[j][e] == 0)      g_Q[idx] = __float2half_rn(v * INV_SCALE);
                        else if (tt[j][e] == 1) g_K[idx] = __float2half_rn(v);
                        else                    g_V[idx] = __float2half_rn(v);
                    }
            }
    } else {
        #pragma unroll
        for (int i = 0; i < 4; i++)
            #pragma unroll
            for (int half = 0; half < 2; half++) {
                int m = m0 + wm * 64 + i * 16 + g + half * 8;
                #pragma unroll
                for (int j = 0; j < 8; j++) {
                    int n = n0 + wn * 64 + j * 8 + 2 * tg;
                    float2 v = make_float2(acc[i][j][half * 2 + 0] + bias[n],
                                           acc[i][j][half * 2 + 1] + bias[n + 1]);
                    *(float2*)(outp + (size_t)m * ND + n) = v;
                }
            }
    }
}

// ---------------------------------------------------------------------------
// Causal flash attention, fp16 mma + ldmatrix, cp.async double-buffered K/V.
// One block = (bh, 64-row q tile), 4 warps.  fp32 softmax/accumulators.
// ---------------------------------------------------------------------------
#define ASTR 72
#define AT   (64 * ASTR)
#define AQ_OFF 0
#define AK_OFF(b)  (AT + (b) * AT)
#define AV_OFF(b)  (3 * AT + (b) * AT)
#define AP_OFF     (5 * AT)
#define ATTN_SMEM  (6 * AT * 2)               // 55296 bytes

__global__ __launch_bounds__(128) void attn_kernel()
{
    extern __shared__ __half asm_[];
    uint32_t sb = smem_u32(asm_);
    __half* Qs = asm_ + AQ_OFF;
    __half* Ps = asm_ + AP_OFF;

    int tid  = threadIdx.x;
    int bh   = blockIdx.y;
    int qt   = blockIdx.x;
    int q0   = qt * 64;
    int warp = tid >> 5, lane = tid & 31;
    int g    = lane >> 2, tg = lane & 3;
    int lrow = lane & 15;
    int lcol = (lane >> 4) * 8;

    int r0 = warp * 16 + g;
    int r1 = r0 + 8;
    int qg0 = q0 + r0, qg1 = q0 + r1;

    const __half* Kg = g_K + (size_t)bh * NS * NDH;
    const __half* Vg = g_V + (size_t)bh * NS * NDH;

    auto prefetch = [&](int kt, int b) {
        const __half* Ksrc = Kg + (size_t)kt * 64 * NDH;
        const __half* Vsrc = Vg + (size_t)kt * 64 * NDH;
        uint32_t kdst = sb + AK_OFF(b) * 2;
        uint32_t vdst = sb + AV_OFF(b) * 2;
        #pragma unroll
        for (int i = 0; i < 4; i++) {
            int ch  = tid + i * 128;
            int row = ch >> 3, q = ch & 7;
            uint32_t doff = (uint32_t)(row * ASTR + q * 8) * 2u;
            cp16(kdst + doff, Ksrc + row * 64 + q * 8);
            cp16(vdst + doff, Vsrc + row * 64 + q * 8);
        }
        cp_commit();
    };

    prefetch(0, 0);

    const __half* Qg = g_Q + ((size_t)bh * NS + q0) * NDH;
    #pragma unroll
    for (int it = 0; it < 4; it++) {
        int ch  = tid + it * 128;
        int row = ch >> 3, q = ch & 7;
        *(uint4*)&Qs[row * ASTR + q * 8] = *(const uint4*)(Qg + (size_t)row * 64 + q * 8);
    }

    float o[8][4];
    #pragma unroll
    for (int j = 0; j < 8; j++)
        #pragma unroll
        for (int e = 0; e < 4; e++) o[j][e] = 0.f;
    float m_run0 = -1e30f, m_run1 = -1e30f;
    float l_run0 = 0.f,    l_run1 = 0.f;

    for (int kt = 0; kt <= qt; kt++) {
        int buf = kt & 1;
        if (kt < qt) prefetch(kt + 1, buf ^ 1);
        if (kt < qt) cp_wait<1>(); else cp_wait<0>();
        __syncthreads();

        uint32_t Kb = sb + AK_OFF(buf) * 2;
        uint32_t Vb = sb + AV_OFF(buf) * 2;
        int k0 = kt * 64;

        // ---- S = Q @ K^T ----
        float sc[8][4];
        #pragma unroll
        for (int j = 0; j < 8; j++)
            #pragma unroll
            for (int e = 0; e < 4; e++) sc[j][e] = 0.f;
        #pragma unroll
        for (int kk = 0; kk < 4; kk++) {
            int kb = kk * 16;
            unsigned a0, a1, a2, a3;
            ldm4(a0, a1, a2, a3,
                 sb + (uint32_t)((warp * 16 + lrow) * ASTR + kb + lcol) * 2u);
            #pragma unroll
            for (int nt = 0; nt < 4; nt++) {
                unsigned r0q, r1q, r2q, r3q;
                ldm4(r0q, r1q, r2q, r3q,
                     Kb + (uint32_t)((nt * 16 + lrow) * ASTR + kb + lcol) * 2u);
                mma16(sc[nt * 2],     a0, a1, a2, a3, r0q, r2q);
                mma16(sc[nt * 2 + 1], a0, a1, a2, a3, r1q, r3q);
            }
        }

        if (kt == qt) {
            #pragma unroll
            for (int j = 0; j < 8; j++)
                #pragma unroll
                for (int e = 0; e < 2; e++) {
                    int kv = k0 + j * 8 + 2 * tg + e;
                    if (kv > qg0) sc[j][e]     = -1e30f;
                    if (kv > qg1) sc[j][2 + e] = -1e30f;
                }
        }

        // ---- online softmax ----
        float ml0 = -1e30f, ml1 = -1e30f;
        #pragma unroll
        for (int j = 0; j < 8; j++) {
            ml0 = fmaxf(ml0, fmaxf(sc[j][0], sc[j][1]));
            ml1 = fmaxf(ml1, fmaxf(sc[j][2], sc[j][3]));
        }
        ml0 = fmaxf(ml0, __shfl_xor_sync(0xffffffffu, ml0, 1));
        ml0 = fmaxf(ml0, __shfl_xor_sync(0xffffffffu, ml0, 2));
        ml1 = fmaxf(ml1, __shfl_xor_sync(0xffffffffu, ml1, 1));
        ml1 = fmaxf(ml1, __shfl_xor_sync(0xffffffffu, ml1, 2));
        float mn0 = fmaxf(m_run0, ml0);
        float mn1 = fmaxf(m_run1, ml1);
        float al0 = __expf(m_run0 - mn0);
        float al1 = __expf(m_run1 - mn1);
        float ls0 = 0.f, ls1 = 0.f;
        #pragma unroll
        for (int j = 0; j < 8; j++) {
            sc[j][0] = __expf(sc[j][0] - mn0);
            sc[j][1] = __expf(sc[j][1] - mn0);
            sc[j][2] = __expf(sc[j][2] - mn1);
            sc[j][3] = __expf(sc[j][3] - mn1);
            ls0 += sc[j][0] + sc[j][1];
            ls1 += sc[j][2] + sc[j][3];
        }
        ls0 += __shfl_xor_sync(0xffffffffu, ls0, 1);
        ls0 += __shfl_xor_sync(0xffffffffu, ls0, 2);
        ls1 += __shfl_xor_sync(0xffffffffu, ls1, 1);
        ls1 += __shfl_xor_sync(0xffffffffu, ls1, 2);
        l_run0 = l_run0 * al0 + ls0;
        l_run1 = l_run1 * al1 + ls1;
        m_run0 = mn0;
        m_run1 = mn1;
        #pragma unroll
        for (int j = 0; j < 8; j++) {
            o[j][0] *= al0;  o[j][1] *= al0;
            o[j][2] *= al1;  o[j][3] *= al1;
        }

        #pragma unroll
        for (int j = 0; j < 8; j++) {
            int cc = j * 8 + 2 * tg;
            *(__half2*)&Ps[r0 * ASTR + cc] = __floats2half2_rn(sc[j][0], sc[j][1]);
            *(__half2*)&Ps[r1 * ASTR + cc] = __floats2half2_rn(sc[j][2], sc[j][3]);
        }
        __syncwarp();

        // ---- O += P @ V ----
        #pragma unroll
        for (int kk = 0; kk < 4; kk++) {
            int kb = kk * 16;
            unsigned a0, a1, a2, a3;
            ldm4(a0, a1, a2, a3,
                 sb + (uint32_t)(AP_OFF * 2) +
                     (uint32_t)((warp * 16 + lrow) * ASTR + kb + lcol) * 2u);
            #pragma unroll
            for (int nt = 0; nt < 4; nt++) {
                unsigned r0q, r1q, r2q, r3q;
                ldm4t(r0q, r1q, r2q, r3q,
                      Vb + (uint32_t)((kb + lrow) * ASTR + nt * 16 + lcol) * 2u);
                mma16(o[nt * 2],     a0, a1, a2, a3, r0q, r1q);
                mma16(o[nt * 2 + 1], a0, a1, a2, a3, r2q, r3q);
            }
        }
        __syncthreads();
    }

    float inv0 = 1.f / l_run0;
    float inv1 = 1.f / l_run1;
    int bi = bh >> 4;
    int h  = bh & 15;
    __half* d0 = g_ctx + ((size_t)(bi * NS) + qg0) * ND + h * NDH;
    __half* d1 = g_ctx + ((size_t)(bi * NS) + qg1) * ND + h * NDH;
    #pragma unroll
    for (int j = 0; j < 8; j++) {
        int cc = j * 8 + 2 * tg;
        *(__half2*)(d0 + cc) = __floats2half2_rn(o[j][0] * inv0, o[j][1] * inv0);
        *(__half2*)(d1 + cc) = __floats2half2_rn(o[j][2] * inv1, o[j][3] * inv1);
    }
}

// ---------------------------------------------------------------------------
// Launch (graph-capturable, allocation-free).
// Inputs: query, mask(unused — causal is static), W_qkv, b_qkv, W_out, b_out.
// ---------------------------------------------------------------------------
extern "C" void kernel_launch(void* const* d_in, const int* in_sizes, int n_in,
                              void* d_out, int out_size)
{
    const float* query = (const float*)d_in[0];
    const float* W_qkv = (const float*)d_in[2];
    const float* b_qkv = (const float*)d_in[3];
    const float* W_out = (const float*)d_in[4];
    const float* b_out = (const float*)d_in[5];
    float* out = (float*)d_out;

    cudaFuncSetAttribute(attn_kernel,
                         cudaFuncAttributeMaxDynamicSharedMemorySize, ATTN_SMEM);
    cudaFuncSetAttribute(mm_gemm_kernel<0>,
                         cudaFuncAttributeMaxDynamicSharedMemorySize, GEMM_SMEM);
    cudaFuncSetAttribute(mm_gemm_kernel<1>,
                         cudaFuncAttributeMaxDynamicSharedMemorySize, GEMM_SMEM);

    __half* Ah;      cudaGetSymbolAddress((void**)&Ah, g_Ah);
    __half* Wt_qkv;  cudaGetSymbolAddress((void**)&Wt_qkv, g_Wt_qkv);
    __half* Wt_out;  cudaGetSymbolAddress((void**)&Wt_out, g_Wt_out);
    __half* ctx;     cudaGetSymbolAddress((void**)&ctx, g_ctx);

    // Prepasses: convert A, transpose+convert weights.
    round_h_kernel<<<(size_t)NM * ND / 1024, 256>>>(query, Ah);
    transpose_h_kernel<<<dim3(N_QKV / 32, ND / 32), 256>>>(W_qkv, Wt_qkv, ND, N_QKV);
    transpose_h_kernel<<<dim3(ND / 32, ND / 32), 256>>>(W_out, Wt_out, ND, ND);

    // QKV projection
    mm_gemm_kernel<0><<<dim3(N_QKV / 128, NM / 128), 128, GEMM_SMEM>>>(
        Ah, Wt_qkv, b_qkv, nullptr);

    // Attention
    attn_kernel<<<dim3(NS / 64, NBH), 128, ATTN_SMEM>>>();

    // Output projection
    mm_gemm_kernel<1><<<dim3(ND / 128, NM / 128), 128, GEMM_SMEM>>>(
        ctx, Wt_out, b_out, out);
}